// round 13
// baseline (speedup 1.0000x reference)
#include <cuda_runtime.h>
#include <math.h>

#define BB   32
#define NSEQ 512
#define DIN  256
#define DH   128
#define NITER 10
#define NM   (NSEQ*NSEQ)
#define HS   (BB*NSEQ*DH)
#define NB   32

// ---------------- device scratch (no runtime allocation) ----------------
static __device__ float  g_H0[HS];
static __device__ float  g_M0[HS];
static __device__ float  g_Hb[2*HS];
static __device__ float  g_Mb[2*HS];
static __device__ float  g_T[HS];
static __device__ float  g_scores[BB*NM];
static __device__ float  g_W[BB*NM];      // Lhat -> in-place GJ result (cols scrambled)
static __device__ float  g_BT[BB*NM];     // BT[j][i] = Binv[i][j]
static __device__ float  g_Y[BB*NM];
static __device__ float  g_F[BB*NSEQ*NB]; // panel transform, row-major [512][NB]
static __device__ float  g_Wp[BB*NB*NSEQ];// swapped panel rows [NB][512]
static __device__ unsigned g_cbits[BB];   // order-encoded max
static __device__ float  g_S[BB*NSEQ];
static __device__ double g_logdet[BB];
static __device__ double g_dotp[BB];
static __device__ float  g_diagB[BB*NSEQ];
static __device__ int    g_piv[BB*NSEQ];
static __device__ int    g_perm[BB*NSEQ]; // Linv labels

__device__ __forceinline__ unsigned enc_f(float v) {
    unsigned u = __float_as_uint(v);
    return (u & 0x80000000u) ? ~u : (u | 0x80000000u);
}
__device__ __forceinline__ float dec_f(unsigned k) {
    return (k & 0x80000000u) ? __uint_as_float(k & 0x7fffffffu) : __uint_as_float(~k);
}

// ---------------- 64x64 GEMM (startup projections only) ----------------
template<bool TA, bool TB, int EPI>
__global__ void __launch_bounds__(256) gemm_k(
    const float* __restrict__ A, const float* __restrict__ B,
    const float* __restrict__ C0, float* __restrict__ C,
    int M, int N, int K, int lda, int ldb, int ldc,
    long sA, long sB, long sC)
{
    int bz = blockIdx.z;
    A += (long)bz * sA;  B += (long)bz * sB;  C += (long)bz * sC;
    __shared__ float As[16][64];
    __shared__ float Bs[16][64];
    int tid = threadIdx.x;
    int i0 = blockIdx.y * 64, j0 = blockIdx.x * 64;
    int tx = tid & 15, ty = tid >> 4;
    float acc[4][4] = {};
    for (int k0 = 0; k0 < K; k0 += 16) {
        if (!TA) {
            int i = tid >> 2, kk = (tid & 3) << 2;
            float4 v = *(const float4*)(A + (long)(i0 + i) * lda + k0 + kk);
            As[kk + 0][i] = v.x; As[kk + 1][i] = v.y; As[kk + 2][i] = v.z; As[kk + 3][i] = v.w;
        } else {
            int kk = tid >> 4, i4 = (tid & 15) << 2;
            float4 v = *(const float4*)(A + (long)(k0 + kk) * lda + i0 + i4);
            *(float4*)&As[kk][i4] = v;
        }
        if (!TB) {
            int kk = tid >> 4, j4 = (tid & 15) << 2;
            float4 v = *(const float4*)(B + (long)(k0 + kk) * ldb + j0 + j4);
            *(float4*)&Bs[kk][j4] = v;
        } else {
            int j = tid >> 2, kk = (tid & 3) << 2;
            float4 v = *(const float4*)(B + (long)(j0 + j) * ldb + k0 + kk);
            Bs[kk + 0][j] = v.x; Bs[kk + 1][j] = v.y; Bs[kk + 2][j] = v.z; Bs[kk + 3][j] = v.w;
        }
        __syncthreads();
        #pragma unroll
        for (int kk = 0; kk < 16; kk++) {
            float4 av = *(const float4*)&As[kk][ty << 2];
            float4 bv = *(const float4*)&Bs[kk][tx << 2];
            float ar[4] = {av.x, av.y, av.z, av.w};
            float br[4] = {bv.x, bv.y, bv.z, bv.w};
            #pragma unroll
            for (int a = 0; a < 4; a++)
                #pragma unroll
                for (int q = 0; q < 4; q++)
                    acc[a][q] = fmaf(ar[a], br[q], acc[a][q]);
        }
        __syncthreads();
    }
    #pragma unroll
    for (int a = 0; a < 4; a++) {
        int row = i0 + (ty << 2) + a;
        long off = (long)row * ldc + j0 + (tx << 2);
        float4 r = make_float4(acc[a][0], acc[a][1], acc[a][2], acc[a][3]);
        if (EPI == 1) {
            float4 bb = *(const float4*)(C0 + j0 + (tx << 2));
            r.x += bb.x; r.y += bb.y; r.z += bb.z; r.w += bb.w;
        }
        *(float4*)(C + off) = r;
    }
}

// ---------------- 128x128 GEMM, 8x8 micro, 256 threads ----------------
// EPI: 0 plain, 2 relu(C0 + acc), 3 store + fused masked atomic max into g_cbits.
// LENA: A has exact-zero rows i>len and zero K-slices k>len (Y / Y^T) ->
//       zero-write skip for i0>len, K loop clamped to len+1 (bitwise exact).
template<bool TA, bool TB, int EPI, bool LENA>
__global__ void __launch_bounds__(256) gemmBig(
    const float* __restrict__ A, const float* __restrict__ B,
    const float* __restrict__ C0, float* __restrict__ C,
    int K, int lda, int ldb, int ldc,
    long sA, long sB, long sC,
    const int* __restrict__ lengths)
{
    int bz = blockIdx.z;
    A += (long)bz * sA;  B += (long)bz * sB;  C += (long)bz * sC;
    __shared__ float As[16][128];
    __shared__ float Bs[16][128];
    int tid = threadIdx.x;
    int i0 = blockIdx.y * 128, j0 = blockIdx.x * 128;
    int ty = tid >> 4, tx = tid & 15;
    int rbase = ty << 3, cbase = tx << 3;

    int Kend = K;
    int len = 0;
    if (LENA || EPI == 3) len = lengths[bz];
    if (LENA) {
        if (i0 > len) {   // all 128 product rows are exact zeros
            #pragma unroll
            for (int a = 0; a < 8; a++) {
                long off = (long)(i0 + rbase + a) * ldc + j0 + cbase;
                *(float4*)(C + off)     = make_float4(0.f, 0.f, 0.f, 0.f);
                *(float4*)(C + off + 4) = make_float4(0.f, 0.f, 0.f, 0.f);
            }
            return;
        }
        Kend = min(K, (len + 16) & ~15);
    }

    float acc[8][8] = {};
    for (int k0 = 0; k0 < Kend; k0 += 16) {
        if (!TA) {
            int i = tid >> 1, kb = (tid & 1) << 3;
            float4 v1 = *(const float4*)(A + (long)(i0 + i) * lda + k0 + kb);
            float4 v2 = *(const float4*)(A + (long)(i0 + i) * lda + k0 + kb + 4);
            As[kb+0][i] = v1.x; As[kb+1][i] = v1.y; As[kb+2][i] = v1.z; As[kb+3][i] = v1.w;
            As[kb+4][i] = v2.x; As[kb+5][i] = v2.y; As[kb+6][i] = v2.z; As[kb+7][i] = v2.w;
        } else {
            int kk = tid >> 4, i8 = (tid & 15) << 3;
            *(float4*)&As[kk][i8]     = *(const float4*)(A + (long)(k0 + kk) * lda + i0 + i8);
            *(float4*)&As[kk][i8 + 4] = *(const float4*)(A + (long)(k0 + kk) * lda + i0 + i8 + 4);
        }
        if (!TB) {
            int kk = tid >> 4, j8 = (tid & 15) << 3;
            *(float4*)&Bs[kk][j8]     = *(const float4*)(B + (long)(k0 + kk) * ldb + j0 + j8);
            *(float4*)&Bs[kk][j8 + 4] = *(const float4*)(B + (long)(k0 + kk) * ldb + j0 + j8 + 4);
        } else {
            int j = tid >> 1, kb = (tid & 1) << 3;
            float4 v1 = *(const float4*)(B + (long)(j0 + j) * ldb + k0 + kb);
            float4 v2 = *(const float4*)(B + (long)(j0 + j) * ldb + k0 + kb + 4);
            Bs[kb+0][j] = v1.x; Bs[kb+1][j] = v1.y; Bs[kb+2][j] = v1.z; Bs[kb+3][j] = v1.w;
            Bs[kb+4][j] = v2.x; Bs[kb+5][j] = v2.y; Bs[kb+6][j] = v2.z; Bs[kb+7][j] = v2.w;
        }
        __syncthreads();
        #pragma unroll
        for (int kk = 0; kk < 16; kk++) {
            float4 a1 = *(const float4*)&As[kk][rbase];
            float4 a2 = *(const float4*)&As[kk][rbase + 4];
            float4 b1 = *(const float4*)&Bs[kk][cbase];
            float4 b2 = *(const float4*)&Bs[kk][cbase + 4];
            float ar[8] = {a1.x, a1.y, a1.z, a1.w, a2.x, a2.y, a2.z, a2.w};
            float br[8] = {b1.x, b1.y, b1.z, b1.w, b2.x, b2.y, b2.z, b2.w};
            #pragma unroll
            for (int a = 0; a < 8; a++)
                #pragma unroll
                for (int q = 0; q < 8; q++)
                    acc[a][q] = fmaf(ar[a], br[q], acc[a][q]);
        }
        __syncthreads();
    }

    #pragma unroll
    for (int a = 0; a < 8; a++) {
        int row = i0 + rbase + a;
        long off = (long)row * ldc + j0 + cbase;
        float4 r1 = make_float4(acc[a][0], acc[a][1], acc[a][2], acc[a][3]);
        float4 r2 = make_float4(acc[a][4], acc[a][5], acc[a][6], acc[a][7]);
        if (EPI == 2) {
            float4 c1 = *(const float4*)(C0 + off);
            float4 c2 = *(const float4*)(C0 + off + 4);
            r1.x = fmaxf(c1.x + r1.x, 0.f); r1.y = fmaxf(c1.y + r1.y, 0.f);
            r1.z = fmaxf(c1.z + r1.z, 0.f); r1.w = fmaxf(c1.w + r1.w, 0.f);
            r2.x = fmaxf(c2.x + r2.x, 0.f); r2.y = fmaxf(c2.y + r2.y, 0.f);
            r2.z = fmaxf(c2.z + r2.z, 0.f); r2.w = fmaxf(c2.w + r2.w, 0.f);
        }
        *(float4*)(C + off)     = r1;
        *(float4*)(C + off + 4) = r2;
    }
    if (EPI == 3) {
        unsigned key = 0u;
        #pragma unroll
        for (int a = 0; a < 8; a++) {
            int h = i0 + rbase + a;
            #pragma unroll
            for (int q = 0; q < 8; q++) {
                int m = j0 + cbase + q;
                if (h <= len && m >= 1 && m <= len && h != m) {
                    unsigned k2 = enc_f(acc[a][q]);
                    if (k2 > key) key = k2;
                }
            }
        }
        #pragma unroll
        for (int o = 16; o; o >>= 1) {
            unsigned ok = __shfl_down_sync(0xffffffffu, key, o);
            if (ok > key) key = ok;
        }
        if ((tid & 31) == 0 && key) atomicMax(&g_cbits[bz], key);
    }
}

__global__ void relu_k(const float* __restrict__ s, float* __restrict__ d, int n) {
    int i = blockIdx.x * blockDim.x + threadIdx.x;
    if (i < n) d[i] = fmaxf(s[i], 0.f);
}

__global__ void init_k() {
    int b = threadIdx.x;
    if (b < BB) { g_cbits[b] = 0u; g_dotp[b] = 0.0; }
}

// ---------------- colsum[j] = sum_{h=1..len, h!=m} exp(s[h,m]-c), m=j+1 ----------------
__global__ void colsum_k(const int* __restrict__ lengths) {
    int b = blockIdx.x, j = threadIdx.x, m = j + 1, len = lengths[b];
    float c = dec_f(g_cbits[b]), s = 0.f;
    if (m < NSEQ && m <= len) {
        const float* sc = g_scores + (size_t)b * NM;
        for (int h = 1; h <= len; h++)
            if (h != m) s += expf(sc[h * NSEQ + m] - c);
    }
    g_S[b * NSEQ + j] = s;
}

// ---------------- build padded 512x512 Lhat ----------------
__global__ void lhat_k(const int* __restrict__ lengths) {
    int i = blockIdx.x, b = blockIdx.y, j = threadIdx.x, len = lengths[b];
    float c = dec_f(g_cbits[b]);
    const float* sc = g_scores + (size_t)b * NM;
    float v;
    if (i == NSEQ - 1)      v = (j == NSEQ - 1) ? 1.f : 0.f;
    else if (j == NSEQ - 1) v = 0.f;
    else if (i == 0) { int m = j + 1; v = (m <= len) ? expf(sc[m] - c) : 0.f; }
    else if (j == i) {
        int m = i + 1;
        float r = (m <= len) ? expf(sc[m] - c) : 0.f;
        v = r + g_S[b * NSEQ + i] + ((m <= len) ? 0.f : 1.f);
    } else {
        int h = i + 1, m = j + 1;
        v = (h <= len && m <= len) ? -expf(sc[h * NSEQ + m] - c) : 0.f;
    }
    g_W[(size_t)b * NM + (size_t)i * NSEQ + j] = v;
}

// ---------------- panel factor: 512xNB panel, one row per thread, in registers ----------------
__global__ void __launch_bounds__(512) panel_k(int k0) {
    int b = blockIdx.x, tid = threadIdx.x;
    float* W = g_W + (size_t)b * NM;
    float a[NB];
    {
        const float4* src = (const float4*)(W + (size_t)tid * NSEQ + k0);
        #pragma unroll
        for (int q = 0; q < NB/4; q++) {
            float4 v = src[q];
            a[4*q] = v.x; a[4*q+1] = v.y; a[4*q+2] = v.z; a[4*q+3] = v.w;
        }
    }
    __shared__ float s_tmpK[NB], s_tmpP[NB];
    __shared__ float red_v[16]; __shared__ int red_i[16];
    __shared__ int sh_p;
    __shared__ int s_pivloc[NB];
    __shared__ double sh_ld;
    __shared__ int s_src[NSEQ];
    __shared__ int s_aff[64];
    __shared__ int s_cnt;
    if (tid == 0) { sh_ld = (k0 == 0) ? 0.0 : g_logdet[b]; s_cnt = 0; }
    s_src[tid] = tid;

    #pragma unroll
    for (int j = 0; j < NB; j++) {
        int k = k0 + j;
        float best = (tid >= k) ? fabsf(a[j]) : -1.f;
        int bi = tid;
        #pragma unroll
        for (int o = 16; o; o >>= 1) {
            float ov = __shfl_down_sync(0xffffffffu, best, o);
            int   oi = __shfl_down_sync(0xffffffffu, bi, o);
            if (ov > best) { best = ov; bi = oi; }
        }
        if ((tid & 31) == 0) { red_v[tid >> 5] = best; red_i[tid >> 5] = bi; }
        __syncthreads();
        if (tid < 32) {
            best = (tid < 16) ? red_v[tid] : -2.f;
            bi   = (tid < 16) ? red_i[tid] : 0;
            #pragma unroll
            for (int o = 8; o; o >>= 1) {
                float ov = __shfl_down_sync(0xffffffffu, best, o);
                int   oi = __shfl_down_sync(0xffffffffu, bi, o);
                if (ov > best) { best = ov; bi = oi; }
            }
            if (tid == 0) { sh_p = bi; s_pivloc[j] = bi; }
        }
        __syncthreads();
        int p = sh_p;
        if (tid == k) {
            for (int jj = 0; jj < NB; jj++) s_tmpK[jj] = a[jj];
        }
        if (tid == p) {
            for (int jj = 0; jj < NB; jj++) s_tmpP[jj] = a[jj];
        }
        __syncthreads();
        const float* prow = (p != k) ? s_tmpP : s_tmpK;
        if (p != k) {
            if (tid == k) {
                for (int jj = 0; jj < NB; jj++) a[jj] = s_tmpP[jj];
            }
            if (tid == p) {
                for (int jj = 0; jj < NB; jj++) a[jj] = s_tmpK[jj];
            }
        }
        float piv = prow[j];
        float pivinv = 1.f / piv;
        if (tid == 0) sh_ld += log(fabs((double)piv));
        if (tid == k) {
            #pragma unroll
            for (int jj = 0; jj < NB; jj++) a[jj] = (jj == j) ? pivinv : prow[jj] * pivinv;
        } else {
            float cm = a[j];
            #pragma unroll
            for (int jj = 0; jj < NB; jj++)
                if (jj != j) a[jj] = fmaf(-cm, prow[jj] * pivinv, a[jj]);
            a[j] = -cm * pivinv;
        }
        __syncthreads();
    }

    {
        float4* fd = (float4*)(g_F + ((size_t)b * NSEQ + tid) * NB);
        #pragma unroll
        for (int q = 0; q < NB/4; q++)
            fd[q] = make_float4(a[4*q], a[4*q+1], a[4*q+2], a[4*q+3]);
    }

    if (tid == 0) {
        for (int j = 0; j < NB; j++) {
            int k = k0 + j, p = s_pivloc[j];
            if (p != k) { int t = s_src[k]; s_src[k] = s_src[p]; s_src[p] = t; }
        }
    }
    __syncthreads();
    if (s_src[tid] != tid) { int idx = atomicAdd(&s_cnt, 1); s_aff[idx] = tid; }
    __syncthreads();
    int cnt = s_cnt;
    {
        float buf[64];
        #pragma unroll
        for (int aa = 0; aa < 64; aa++)
            if (aa < cnt) buf[aa] = W[(size_t)s_src[s_aff[aa]] * NSEQ + tid];
        #pragma unroll
        for (int aa = 0; aa < 64; aa++)
            if (aa < cnt) W[(size_t)s_aff[aa] * NSEQ + tid] = buf[aa];
    }
    __syncthreads();

    for (int t = tid; t < NB * NSEQ; t += 512) {
        int r = t >> 9, c4 = t & 511;
        g_Wp[(size_t)b * NB * NSEQ + t] = W[(size_t)(k0 + r) * NSEQ + c4];
    }
    {
        float4* wd = (float4*)(W + (size_t)tid * NSEQ + k0);
        #pragma unroll
        for (int q = 0; q < NB/4; q++)
            wd[q] = make_float4(a[4*q], a[4*q+1], a[4*q+2], a[4*q+3]);
    }
    if (tid < NB) g_piv[b * NSEQ + k0 + tid] = s_pivloc[tid];
    if (tid == 0) g_logdet[b] = sh_ld;
}

// ---------------- rank-NB trailing update: W = base + F*Wp, full chip ----------------
__global__ void __launch_bounds__(256) upd_k(int k0) {
    int b = blockIdx.z;
    float* W = g_W + (size_t)b * NM;
    const float* F  = g_F  + (size_t)b * NSEQ * NB;
    const float* Wp = g_Wp + (size_t)b * NB * NSEQ;
    __shared__ float Fs[NB][64];
    __shared__ float Bs[NB][64];
    int tid = threadIdx.x;
    int i0 = blockIdx.y * 64, j0 = blockIdx.x * 64;
    {
        int i = tid >> 2, kk = (tid & 3) << 3;
        float4 v1 = *(const float4*)(F + (size_t)(i0 + i) * NB + kk);
        float4 v2 = *(const float4*)(F + (size_t)(i0 + i) * NB + kk + 4);
        Fs[kk+0][i] = v1.x; Fs[kk+1][i] = v1.y; Fs[kk+2][i] = v1.z; Fs[kk+3][i] = v1.w;
        Fs[kk+4][i] = v2.x; Fs[kk+5][i] = v2.y; Fs[kk+6][i] = v2.z; Fs[kk+7][i] = v2.w;
    }
    {
        int kk = tid >> 3, j8 = (tid & 7) << 3;
        *(float4*)&Bs[kk][j8]     = *(const float4*)(Wp + (size_t)kk * NSEQ + j0 + j8);
        *(float4*)&Bs[kk][j8 + 4] = *(const float4*)(Wp + (size_t)kk * NSEQ + j0 + j8 + 4);
    }
    __syncthreads();
    int tx = tid & 15, ty = tid >> 4;
    float acc[4][4] = {};
    #pragma unroll
    for (int kk = 0; kk < NB; kk++) {
        float4 av = *(const float4*)&Fs[kk][ty << 2];
        float4 bv = *(const float4*)&Bs[kk][tx << 2];
        float ar[4] = {av.x, av.y, av.z, av.w};
        float br[4] = {bv.x, bv.y, bv.z, bv.w};
        #pragma unroll
        for (int a = 0; a < 4; a++)
            #pragma unroll
            for (int q = 0; q < 4; q++)
                acc[a][q] = fmaf(ar[a], br[q], acc[a][q]);
    }
    int col = j0 + (tx << 2);
    bool pcol = (col >= k0 && col < k0 + NB);
    if (pcol) return;
    #pragma unroll
    for (int a = 0; a < 4; a++) {
        int row = i0 + (ty << 2) + a;
        bool prow = (row >= k0 && row < k0 + NB);
        float4* wp4 = (float4*)(W + (size_t)row * NSEQ + col);
        float4 r = make_float4(acc[a][0], acc[a][1], acc[a][2], acc[a][3]);
        if (!prow) {
            float4 base = *wp4;
            r.x += base.x; r.y += base.y; r.z += base.z; r.w += base.w;
        }
        *wp4 = r;
    }
}

// ---------------- resolve labels: g_perm = Linv (Linv[L[j]] = j) ----------------
__global__ void __launch_bounds__(512) labels_k() {
    int b = blockIdx.x, tid = threadIdx.x;
    __shared__ int s_L[NSEQ];
    if (tid == 0) {
        for (int j = 0; j < NSEQ; j++) s_L[j] = j;
        for (int k = NSEQ - 1; k >= 0; k--) {
            int p = g_piv[b * NSEQ + k];
            if (p != k) { int t = s_L[k]; s_L[k] = s_L[p]; s_L[p] = t; }
        }
    }
    __syncthreads();
    g_perm[b * NSEQ + s_L[tid]] = tid;
}

// ---------------- coalesced permuted transpose + diag: BT[Linv[j]][i] = C[i][j] ----------------
__global__ void permT_k() {
    int b = blockIdx.z;
    const float* C = g_W + (size_t)b * NM;
    float* BT = g_BT + (size_t)b * NM;
    const int* Linv = g_perm + b * NSEQ;
    __shared__ float sm[32][33];
    int i0 = blockIdx.y * 32, j0 = blockIdx.x * 32;
    int tx = threadIdx.x, ty = threadIdx.y;
    #pragma unroll
    for (int k = 0; k < 4; k++)
        sm[ty + 8*k][tx] = C[(size_t)(i0 + ty + 8*k) * NSEQ + j0 + tx];
    __syncthreads();
    #pragma unroll
    for (int k = 0; k < 4; k++) {
        int j = j0 + ty + 8*k;
        int lj = Linv[j];
        float v = sm[tx][ty + 8*k];
        BT[(size_t)lj * NSEQ + i0 + tx] = v;
        if (lj == i0 + tx) g_diagB[b * NSEQ + lj] = v;
    }
}

// ---------------- marginals Y + fp64 dot(Y, scores) ----------------
__global__ void __launch_bounds__(512) y_k(const int* __restrict__ lengths) {
    int h = blockIdx.x, b = blockIdx.y, m = threadIdx.x;
    int len = lengths[b];
    float c = dec_f(g_cbits[b]);
    float s = g_scores[(size_t)b * NM + (size_t)h * NSEQ + m];
    float y = 0.f;
    if (h <= len && m >= 1 && m <= len && h != m) {
        float A = expf(s - c);
        float diag = (m >= 2) ? g_diagB[b * NSEQ + (m - 1)] : 0.f;
        float G;
        if (h == 0) G = g_BT[(size_t)b * NM + (m - 1)] + diag;   // BT row 0 = Binv[:,0]
        else        G = diag - ((h >= 2) ? g_BT[(size_t)b * NM + (size_t)(h - 1) * NSEQ + (m - 1)] : 0.f);
        y = A * G;
    }
    g_Y[(size_t)b * NM + (size_t)h * NSEQ + m] = y;

    float v = y * s;
    #pragma unroll
    for (int o = 16; o; o >>= 1) v += __shfl_down_sync(0xffffffffu, v, o);
    __shared__ float ws[16];
    if ((m & 31) == 0) ws[m >> 5] = v;
    __syncthreads();
    if (m < 16) {
        v = ws[m];
        #pragma unroll
        for (int o = 8; o; o >>= 1) v += __shfl_down_sync(0xffffu, v, o);
        if (m == 0) atomicAdd(&g_dotp[b], (double)v);
    }
}

__global__ void fin_k(const int* __restrict__ lengths, float* __restrict__ out) {
    int b = threadIdx.x;
    if (b < BB) {
        float logZ = (float)g_logdet[b] + (float)lengths[b] * dec_f(g_cbits[b]);
        out[(size_t)BB * NM + b] = logZ;
        out[(size_t)2 * BB * NM + BB + b] = logZ - (float)g_dotp[b];
    }
}

extern "C" void kernel_launch(void* const* d_in, const int* in_sizes, int n_in,
                              void* d_out, int out_size) {
    const float* Xh = (const float*)d_in[0];
    const float* Xm = (const float*)d_in[1];
    const int*   lengths = (const int*)d_in[2];
    const float* Wh = (const float*)d_in[3];
    const float* bh = (const float*)d_in[4];
    const float* Wm = (const float*)d_in[5];
    const float* bm = (const float*)d_in[6];
    const float* V  = (const float*)d_in[7];
    float* out = (float*)d_out;

    void* p;
    cudaGetSymbolAddress(&p, g_H0);     float* pH0 = (float*)p;
    cudaGetSymbolAddress(&p, g_M0);     float* pM0 = (float*)p;
    cudaGetSymbolAddress(&p, g_Hb);     float* pHb = (float*)p;
    cudaGetSymbolAddress(&p, g_Mb);     float* pMb = (float*)p;
    cudaGetSymbolAddress(&p, g_T);      float* pT  = (float*)p;
    cudaGetSymbolAddress(&p, g_scores); float* pSc = (float*)p;
    cudaGetSymbolAddress(&p, g_Y);      float* pY  = (float*)p;

    dim3 gProj(DH / 64, (BB * NSEQ) / 64, 1);

    gemm_k<false, true, 1><<<gProj, 256>>>(Xh, Wh, bh, pH0, BB*NSEQ, DH, DIN, DIN, DIN, DH, 0, 0, 0);
    gemm_k<false, true, 1><<<gProj, 256>>>(Xm, Wm, bm, pM0, BB*NSEQ, DH, DIN, DIN, DIN, DH, 0, 0, 0);
    relu_k<<<(HS + 255) / 256, 256>>>(pH0, pHb, HS);
    relu_k<<<(HS + 255) / 256, 256>>>(pM0, pMb, HS);

    dim3 gBig128(1, (BB * NSEQ) / 128, 1);        // flattened 16384x128 outputs
    dim3 gScB(NSEQ / 128, NSEQ / 128, BB);        // (4,4,32) batched 512x512
    dim3 gYMB(1, NSEQ / 128, BB);                 // (1,4,32) batched 512x128

    for (int it = 0; it < NITER; it++) {
        float* H = pHb + (size_t)(it & 1) * HS;
        float* M = pMb + (size_t)(it & 1) * HS;
        init_k<<<1, BB>>>();
        // T = H @ V
        gemmBig<false, false, 0, false><<<gBig128, 256>>>(H, V, nullptr, pT, DH, DH, DH, DH, 0, 0, 0, nullptr);
        // scores = T @ M^T (batched) + fused masked max
        gemmBig<false, true, 3, false><<<gScB, 256>>>(pT, M, nullptr, pSc, DH, DH, DH, NSEQ,
                                                      (long)NSEQ*DH, (long)NSEQ*DH, (long)NM, lengths);
        colsum_k<<<BB, NSEQ>>>(lengths);
        lhat_k<<<dim3(NSEQ, BB), NSEQ>>>(lengths);
        for (int k0 = 0; k0 < NSEQ; k0 += NB) {
            panel_k<<<BB, 512>>>(k0);
            upd_k<<<dim3(8, 8, BB), 256>>>(k0);
        }
        labels_k<<<BB, 512>>>();
        permT_k<<<dim3(16, 16, BB), dim3(32, 8)>>>();
        y_k<<<dim3(NSEQ, BB), NSEQ>>>(lengths);

        if (it < NITER - 1) {
            float* Hn = pHb + (size_t)((it + 1) & 1) * HS;
            float* Mn = pMb + (size_t)((it + 1) & 1) * HS;
            // T = Y @ M (batched, len-pruned)
            gemmBig<false, false, 0, true><<<gYMB, 256>>>(pY, M, nullptr, pT, NSEQ, NSEQ, DH, DH,
                                                          (long)NM, (long)NSEQ*DH, (long)NSEQ*DH, lengths);
            // Hn = relu(H0 + T @ V^T)
            gemmBig<false, true, 2, false><<<gBig128, 256>>>(pT, V, pH0, Hn, DH, DH, DH, DH, 0, 0, 0, nullptr);
            // T = Y^T @ H (batched, len-pruned)
            gemmBig<true, false, 0, true><<<gYMB, 256>>>(pY, H, nullptr, pT, NSEQ, NSEQ, DH, DH,
                                                         (long)NM, (long)NSEQ*DH, (long)NSEQ*DH, lengths);
            // Mn = relu(M0 + T @ V)
            gemmBig<false, false, 2, false><<<gBig128, 256>>>(pT, V, pM0, Mn, DH, DH, DH, DH, 0, 0, 0, nullptr);
        }
    }

    fin_k<<<1, BB>>>(lengths, out);
    cudaMemcpyAsync(out, pSc, (size_t)BB * NM * sizeof(float), cudaMemcpyDeviceToDevice, 0);
    cudaMemcpyAsync(out + (size_t)BB * NM + BB, pY, (size_t)BB * NM * sizeof(float), cudaMemcpyDeviceToDevice, 0);
}

// round 14
// speedup vs baseline: 1.0179x; 1.0179x over previous
#include <cuda_runtime.h>
#include <math.h>

#define BB   32
#define NSEQ 512
#define DIN  256
#define DH   128
#define NITER 10
#define NM   (NSEQ*NSEQ)
#define HS   (BB*NSEQ*DH)
#define NB   32

// ---------------- device scratch (no runtime allocation) ----------------
static __device__ float  g_H0[HS];
static __device__ float  g_M0[HS];
static __device__ float  g_Hb[2*HS];
static __device__ float  g_Mb[2*HS];
static __device__ float  g_T[HS];
static __device__ float  g_W[BB*NM];      // Lhat -> in-place GJ result (cols scrambled)
static __device__ float  g_BT[BB*NM];     // BT[j][i] = Binv[i][j]
static __device__ float  g_F[BB*NSEQ*NB]; // panel transform, row-major [512][NB]
static __device__ float  g_Wp[BB*NB*NSEQ];// swapped panel rows [NB][512]
static __device__ unsigned g_cbits[BB];   // order-encoded max
static __device__ float  g_S[BB*NSEQ];    // At row 0 (h=1) values, stashed by lhat
static __device__ double g_logdet[BB];
static __device__ double g_dotp[BB];
static __device__ float  g_diagB[BB*NSEQ];
static __device__ int    g_piv[BB*NSEQ];
static __device__ int    g_perm[BB*NSEQ]; // Linv labels

__device__ __forceinline__ unsigned enc_f(float v) {
    unsigned u = __float_as_uint(v);
    return (u & 0x80000000u) ? ~u : (u | 0x80000000u);
}
__device__ __forceinline__ float dec_f(unsigned k) {
    return (k & 0x80000000u) ? __uint_as_float(k & 0x7fffffffu) : __uint_as_float(~k);
}

// ---------------- 64x64 GEMM (startup projections only) ----------------
template<bool TA, bool TB, int EPI>
__global__ void __launch_bounds__(256) gemm_k(
    const float* __restrict__ A, const float* __restrict__ B,
    const float* __restrict__ C0, float* __restrict__ C,
    int M, int N, int K, int lda, int ldb, int ldc,
    long sA, long sB, long sC)
{
    int bz = blockIdx.z;
    A += (long)bz * sA;  B += (long)bz * sB;  C += (long)bz * sC;
    __shared__ float As[16][64];
    __shared__ float Bs[16][64];
    int tid = threadIdx.x;
    int i0 = blockIdx.y * 64, j0 = blockIdx.x * 64;
    int tx = tid & 15, ty = tid >> 4;
    float acc[4][4] = {};
    for (int k0 = 0; k0 < K; k0 += 16) {
        if (!TA) {
            int i = tid >> 2, kk = (tid & 3) << 2;
            float4 v = *(const float4*)(A + (long)(i0 + i) * lda + k0 + kk);
            As[kk + 0][i] = v.x; As[kk + 1][i] = v.y; As[kk + 2][i] = v.z; As[kk + 3][i] = v.w;
        } else {
            int kk = tid >> 4, i4 = (tid & 15) << 2;
            float4 v = *(const float4*)(A + (long)(k0 + kk) * lda + i0 + i4);
            *(float4*)&As[kk][i4] = v;
        }
        if (!TB) {
            int kk = tid >> 4, j4 = (tid & 15) << 2;
            float4 v = *(const float4*)(B + (long)(k0 + kk) * ldb + j0 + j4);
            *(float4*)&Bs[kk][j4] = v;
        } else {
            int j = tid >> 2, kk = (tid & 3) << 2;
            float4 v = *(const float4*)(B + (long)(j0 + j) * ldb + k0 + kk);
            Bs[kk + 0][j] = v.x; Bs[kk + 1][j] = v.y; Bs[kk + 2][j] = v.z; Bs[kk + 3][j] = v.w;
        }
        __syncthreads();
        #pragma unroll
        for (int kk = 0; kk < 16; kk++) {
            float4 av = *(const float4*)&As[kk][ty << 2];
            float4 bv = *(const float4*)&Bs[kk][tx << 2];
            float ar[4] = {av.x, av.y, av.z, av.w};
            float br[4] = {bv.x, bv.y, bv.z, bv.w};
            #pragma unroll
            for (int a = 0; a < 4; a++)
                #pragma unroll
                for (int q = 0; q < 4; q++)
                    acc[a][q] = fmaf(ar[a], br[q], acc[a][q]);
        }
        __syncthreads();
    }
    #pragma unroll
    for (int a = 0; a < 4; a++) {
        int row = i0 + (ty << 2) + a;
        long off = (long)row * ldc + j0 + (tx << 2);
        float4 r = make_float4(acc[a][0], acc[a][1], acc[a][2], acc[a][3]);
        if (EPI == 1) {
            float4 bb = *(const float4*)(C0 + j0 + (tx << 2));
            r.x += bb.x; r.y += bb.y; r.z += bb.z; r.w += bb.w;
        }
        *(float4*)(C + off) = r;
    }
}

// ---------------- 128x128 GEMM, 8x8 micro, 256 threads ----------------
template<bool TA, bool TB, int EPI, bool LENA>
__global__ void __launch_bounds__(256) gemmBig(
    const float* __restrict__ A, const float* __restrict__ B,
    const float* __restrict__ C0, float* __restrict__ C,
    int K, int lda, int ldb, int ldc,
    long sA, long sB, long sC,
    const int* __restrict__ lengths)
{
    int bz = blockIdx.z;
    A += (long)bz * sA;  B += (long)bz * sB;  C += (long)bz * sC;
    __shared__ float As[16][128];
    __shared__ float Bs[16][128];
    int tid = threadIdx.x;
    int i0 = blockIdx.y * 128, j0 = blockIdx.x * 128;
    int ty = tid >> 4, tx = tid & 15;
    int rbase = ty << 3, cbase = tx << 3;

    int Kend = K;
    int len = 0;
    if (LENA || EPI == 3) len = lengths[bz];
    if (LENA) {
        if (i0 > len) {
            #pragma unroll
            for (int a = 0; a < 8; a++) {
                long off = (long)(i0 + rbase + a) * ldc + j0 + cbase;
                *(float4*)(C + off)     = make_float4(0.f, 0.f, 0.f, 0.f);
                *(float4*)(C + off + 4) = make_float4(0.f, 0.f, 0.f, 0.f);
            }
            return;
        }
        Kend = min(K, (len + 16) & ~15);
    }

    float acc[8][8] = {};
    for (int k0 = 0; k0 < Kend; k0 += 16) {
        if (!TA) {
            int i = tid >> 1, kb = (tid & 1) << 3;
            float4 v1 = *(const float4*)(A + (long)(i0 + i) * lda + k0 + kb);
            float4 v2 = *(const float4*)(A + (long)(i0 + i) * lda + k0 + kb + 4);
            As[kb+0][i] = v1.x; As[kb+1][i] = v1.y; As[kb+2][i] = v1.z; As[kb+3][i] = v1.w;
            As[kb+4][i] = v2.x; As[kb+5][i] = v2.y; As[kb+6][i] = v2.z; As[kb+7][i] = v2.w;
        } else {
            int kk = tid >> 4, i8 = (tid & 15) << 3;
            *(float4*)&As[kk][i8]     = *(const float4*)(A + (long)(k0 + kk) * lda + i0 + i8);
            *(float4*)&As[kk][i8 + 4] = *(const float4*)(A + (long)(k0 + kk) * lda + i0 + i8 + 4);
        }
        if (!TB) {
            int kk = tid >> 4, j8 = (tid & 15) << 3;
            *(float4*)&Bs[kk][j8]     = *(const float4*)(B + (long)(k0 + kk) * ldb + j0 + j8);
            *(float4*)&Bs[kk][j8 + 4] = *(const float4*)(B + (long)(k0 + kk) * ldb + j0 + j8 + 4);
        } else {
            int j = tid >> 1, kb = (tid & 1) << 3;
            float4 v1 = *(const float4*)(B + (long)(j0 + j) * ldb + k0 + kb);
            float4 v2 = *(const float4*)(B + (long)(j0 + j) * ldb + k0 + kb + 4);
            Bs[kb+0][j] = v1.x; Bs[kb+1][j] = v1.y; Bs[kb+2][j] = v1.z; Bs[kb+3][j] = v1.w;
            Bs[kb+4][j] = v2.x; Bs[kb+5][j] = v2.y; Bs[kb+6][j] = v2.z; Bs[kb+7][j] = v2.w;
        }
        __syncthreads();
        #pragma unroll
        for (int kk = 0; kk < 16; kk++) {
            float4 a1 = *(const float4*)&As[kk][rbase];
            float4 a2 = *(const float4*)&As[kk][rbase + 4];
            float4 b1 = *(const float4*)&Bs[kk][cbase];
            float4 b2 = *(const float4*)&Bs[kk][cbase + 4];
            float ar[8] = {a1.x, a1.y, a1.z, a1.w, a2.x, a2.y, a2.z, a2.w};
            float br[8] = {b1.x, b1.y, b1.z, b1.w, b2.x, b2.y, b2.z, b2.w};
            #pragma unroll
            for (int a = 0; a < 8; a++)
                #pragma unroll
                for (int q = 0; q < 8; q++)
                    acc[a][q] = fmaf(ar[a], br[q], acc[a][q]);
        }
        __syncthreads();
    }

    #pragma unroll
    for (int a = 0; a < 8; a++) {
        int row = i0 + rbase + a;
        long off = (long)row * ldc + j0 + cbase;
        float4 r1 = make_float4(acc[a][0], acc[a][1], acc[a][2], acc[a][3]);
        float4 r2 = make_float4(acc[a][4], acc[a][5], acc[a][6], acc[a][7]);
        if (EPI == 2) {
            float4 c1 = *(const float4*)(C0 + off);
            float4 c2 = *(const float4*)(C0 + off + 4);
            r1.x = fmaxf(c1.x + r1.x, 0.f); r1.y = fmaxf(c1.y + r1.y, 0.f);
            r1.z = fmaxf(c1.z + r1.z, 0.f); r1.w = fmaxf(c1.w + r1.w, 0.f);
            r2.x = fmaxf(c2.x + r2.x, 0.f); r2.y = fmaxf(c2.y + r2.y, 0.f);
            r2.z = fmaxf(c2.z + r2.z, 0.f); r2.w = fmaxf(c2.w + r2.w, 0.f);
        }
        *(float4*)(C + off)     = r1;
        *(float4*)(C + off + 4) = r2;
    }
    if (EPI == 3) {
        unsigned key = 0u;
        #pragma unroll
        for (int a = 0; a < 8; a++) {
            int h = i0 + rbase + a;
            #pragma unroll
            for (int q = 0; q < 8; q++) {
                int m = j0 + cbase + q;
                if (h <= len && m >= 1 && m <= len && h != m) {
                    unsigned k2 = enc_f(acc[a][q]);
                    if (k2 > key) key = k2;
                }
            }
        }
        #pragma unroll
        for (int o = 16; o; o >>= 1) {
            unsigned ok = __shfl_down_sync(0xffffffffu, key, o);
            if (ok > key) key = ok;
        }
        if ((tid & 31) == 0 && key) atomicMax(&g_cbits[bz], key);
    }
}

__global__ void relu_k(const float* __restrict__ s, float* __restrict__ d, int n) {
    int i = blockIdx.x * blockDim.x + threadIdx.x;
    if (i < n) d[i] = fmaxf(s[i], 0.f);
}

__global__ void init_k() {
    int b = threadIdx.x;
    if (b < BB) { g_cbits[b] = 0u; g_dotp[b] = 0.0; }
}

// ---------------- build padded 512x512 Lhat (diag WITHOUT colsum S);
//                  i==0 CTA also stashes At row 0 (h=1) into g_S ----------------
__global__ void lhat_k(const int* __restrict__ lengths, const float* __restrict__ scores) {
    int i = blockIdx.x, b = blockIdx.y, j = threadIdx.x, len = lengths[b];
    float c = dec_f(g_cbits[b]);
    const float* sc = scores + (size_t)b * NM;
    float v;
    if (i == NSEQ - 1)      v = (j == NSEQ - 1) ? 1.f : 0.f;
    else if (j == NSEQ - 1) v = 0.f;
    else if (i == 0) {
        int m = j + 1;
        v = (m <= len) ? __expf(sc[m] - c) : 0.f;   // r[j]
        // stash At[0][j] = A[1][m] (h=1; h==m excluded when j==0)
        float r1 = (m <= len && m != 1) ? __expf(sc[NSEQ + m] - c) : 0.f;
        g_S[b * NSEQ + j] = r1;
    }
    else if (j == i) {
        int m = i + 1;
        float r = (m <= len) ? __expf(sc[m] - c) : 0.f;
        v = r + ((m <= len) ? 0.f : 1.f);           // S added later by diagfix_k
    } else {
        int h = i + 1, m = j + 1;
        v = (h <= len && m <= len) ? -__expf(sc[h * NSEQ + m] - c) : 0.f;
    }
    g_W[(size_t)b * NM + (size_t)i * NSEQ + j] = v;
}

// ---------------- diag += S, with S_j = row1[j] - sum_{h in [1,510], h!=j} W[h][j] ----------------
__global__ void __launch_bounds__(1024) diagfix_k() {
    int b = blockIdx.y;
    int x = threadIdx.x, y = threadIdx.y;   // (32,32)
    int j = blockIdx.x * 32 + x;
    float* W = g_W + (size_t)b * NM;
    float part = 0.f;
    for (int h = 1 + y; h < NSEQ - 1; h += 32)
        if (h != j) part += W[(size_t)h * NSEQ + j];
    __shared__ float red[32][33];
    red[y][x] = part;
    __syncthreads();
    if (y == 0 && j >= 1 && j <= NSEQ - 2) {
        float s = 0.f;
        #pragma unroll
        for (int k = 0; k < 32; k++) s += red[k][x];
        float S = g_S[b * NSEQ + j] - s;
        W[(size_t)j * NSEQ + j] += S;
    }
}

// ---------------- panel factor: 512xNB panel, one row per thread, in registers ----------------
__global__ void __launch_bounds__(512) panel_k(int k0) {
    int b = blockIdx.x, tid = threadIdx.x;
    float* W = g_W + (size_t)b * NM;
    float a[NB];
    {
        const float4* src = (const float4*)(W + (size_t)tid * NSEQ + k0);
        #pragma unroll
        for (int q = 0; q < NB/4; q++) {
            float4 v = src[q];
            a[4*q] = v.x; a[4*q+1] = v.y; a[4*q+2] = v.z; a[4*q+3] = v.w;
        }
    }
    __shared__ float s_tmpK[NB], s_tmpP[NB];
    __shared__ float red_v[16]; __shared__ int red_i[16];
    __shared__ int sh_p;
    __shared__ int s_pivloc[NB];
    __shared__ double sh_ld;
    __shared__ int s_src[NSEQ];
    __shared__ int s_aff[64];
    __shared__ int s_cnt;
    if (tid == 0) { sh_ld = (k0 == 0) ? 0.0 : g_logdet[b]; s_cnt = 0; }
    s_src[tid] = tid;

    #pragma unroll
    for (int j = 0; j < NB; j++) {
        int k = k0 + j;
        float best = (tid >= k) ? fabsf(a[j]) : -1.f;
        int bi = tid;
        #pragma unroll
        for (int o = 16; o; o >>= 1) {
            float ov = __shfl_down_sync(0xffffffffu, best, o);
            int   oi = __shfl_down_sync(0xffffffffu, bi, o);
            if (ov > best) { best = ov; bi = oi; }
        }
        if ((tid & 31) == 0) { red_v[tid >> 5] = best; red_i[tid >> 5] = bi; }
        __syncthreads();
        if (tid < 32) {
            best = (tid < 16) ? red_v[tid] : -2.f;
            bi   = (tid < 16) ? red_i[tid] : 0;
            #pragma unroll
            for (int o = 8; o; o >>= 1) {
                float ov = __shfl_down_sync(0xffffffffu, best, o);
                int   oi = __shfl_down_sync(0xffffffffu, bi, o);
                if (ov > best) { best = ov; bi = oi; }
            }
            if (tid == 0) { sh_p = bi; s_pivloc[j] = bi; }
        }
        __syncthreads();
        int p = sh_p;
        if (tid == k) {
            for (int jj = 0; jj < NB; jj++) s_tmpK[jj] = a[jj];
        }
        if (tid == p) {
            for (int jj = 0; jj < NB; jj++) s_tmpP[jj] = a[jj];
        }
        __syncthreads();
        const float* prow = (p != k) ? s_tmpP : s_tmpK;
        if (p != k) {
            if (tid == k) {
                for (int jj = 0; jj < NB; jj++) a[jj] = s_tmpP[jj];
            }
            if (tid == p) {
                for (int jj = 0; jj < NB; jj++) a[jj] = s_tmpK[jj];
            }
        }
        float piv = prow[j];
        float pivinv = 1.f / piv;
        if (tid == 0) sh_ld += log(fabs((double)piv));
        if (tid == k) {
            #pragma unroll
            for (int jj = 0; jj < NB; jj++) a[jj] = (jj == j) ? pivinv : prow[jj] * pivinv;
        } else {
            float cm = a[j];
            #pragma unroll
            for (int jj = 0; jj < NB; jj++)
                if (jj != j) a[jj] = fmaf(-cm, prow[jj] * pivinv, a[jj]);
            a[j] = -cm * pivinv;
        }
        __syncthreads();
    }

    {
        float4* fd = (float4*)(g_F + ((size_t)b * NSEQ + tid) * NB);
        #pragma unroll
        for (int q = 0; q < NB/4; q++)
            fd[q] = make_float4(a[4*q], a[4*q+1], a[4*q+2], a[4*q+3]);
    }

    if (tid == 0) {
        for (int j = 0; j < NB; j++) {
            int k = k0 + j, p = s_pivloc[j];
            if (p != k) { int t = s_src[k]; s_src[k] = s_src[p]; s_src[p] = t; }
        }
    }
    __syncthreads();
    if (s_src[tid] != tid) { int idx = atomicAdd(&s_cnt, 1); s_aff[idx] = tid; }
    __syncthreads();
    int cnt = s_cnt;
    {
        float buf[64];
        #pragma unroll
        for (int aa = 0; aa < 64; aa++)
            if (aa < cnt) buf[aa] = W[(size_t)s_src[s_aff[aa]] * NSEQ + tid];
        #pragma unroll
        for (int aa = 0; aa < 64; aa++)
            if (aa < cnt) W[(size_t)s_aff[aa] * NSEQ + tid] = buf[aa];
    }
    __syncthreads();

    for (int t = tid; t < NB * NSEQ; t += 512) {
        int r = t >> 9, c4 = t & 511;
        g_Wp[(size_t)b * NB * NSEQ + t] = W[(size_t)(k0 + r) * NSEQ + c4];
    }
    {
        float4* wd = (float4*)(W + (size_t)tid * NSEQ + k0);
        #pragma unroll
        for (int q = 0; q < NB/4; q++)
            wd[q] = make_float4(a[4*q], a[4*q+1], a[4*q+2], a[4*q+3]);
    }
    if (tid < NB) g_piv[b * NSEQ + k0 + tid] = s_pivloc[tid];
    if (tid == 0) g_logdet[b] = sh_ld;
}

// ---------------- rank-NB trailing update: W = base + F*Wp, full chip ----------------
__global__ void __launch_bounds__(256) upd_k(int k0) {
    int b = blockIdx.z;
    float* W = g_W + (size_t)b * NM;
    const float* F  = g_F  + (size_t)b * NSEQ * NB;
    const float* Wp = g_Wp + (size_t)b * NB * NSEQ;
    __shared__ float Fs[NB][64];
    __shared__ float Bs[NB][64];
    int tid = threadIdx.x;
    int i0 = blockIdx.y * 64, j0 = blockIdx.x * 64;
    {
        int i = tid >> 2, kk = (tid & 3) << 3;
        float4 v1 = *(const float4*)(F + (size_t)(i0 + i) * NB + kk);
        float4 v2 = *(const float4*)(F + (size_t)(i0 + i) * NB + kk + 4);
        Fs[kk+0][i] = v1.x; Fs[kk+1][i] = v1.y; Fs[kk+2][i] = v1.z; Fs[kk+3][i] = v1.w;
        Fs[kk+4][i] = v2.x; Fs[kk+5][i] = v2.y; Fs[kk+6][i] = v2.z; Fs[kk+7][i] = v2.w;
    }
    {
        int kk = tid >> 3, j8 = (tid & 7) << 3;
        *(float4*)&Bs[kk][j8]     = *(const float4*)(Wp + (size_t)kk * NSEQ + j0 + j8);
        *(float4*)&Bs[kk][j8 + 4] = *(const float4*)(Wp + (size_t)kk * NSEQ + j0 + j8 + 4);
    }
    __syncthreads();
    int tx = tid & 15, ty = tid >> 4;
    float acc[4][4] = {};
    #pragma unroll
    for (int kk = 0; kk < NB; kk++) {
        float4 av = *(const float4*)&Fs[kk][ty << 2];
        float4 bv = *(const float4*)&Bs[kk][tx << 2];
        float ar[4] = {av.x, av.y, av.z, av.w};
        float br[4] = {bv.x, bv.y, bv.z, bv.w};
        #pragma unroll
        for (int a = 0; a < 4; a++)
            #pragma unroll
            for (int q = 0; q < 4; q++)
                acc[a][q] = fmaf(ar[a], br[q], acc[a][q]);
    }
    int col = j0 + (tx << 2);
    bool pcol = (col >= k0 && col < k0 + NB);
    if (pcol) return;
    #pragma unroll
    for (int a = 0; a < 4; a++) {
        int row = i0 + (ty << 2) + a;
        bool prow = (row >= k0 && row < k0 + NB);
        float4* wp4 = (float4*)(W + (size_t)row * NSEQ + col);
        float4 r = make_float4(acc[a][0], acc[a][1], acc[a][2], acc[a][3]);
        if (!prow) {
            float4 base = *wp4;
            r.x += base.x; r.y += base.y; r.z += base.z; r.w += base.w;
        }
        *wp4 = r;
    }
}

// ---------------- resolve labels: g_perm = Linv (Linv[L[j]] = j) ----------------
__global__ void __launch_bounds__(512) labels_k() {
    int b = blockIdx.x, tid = threadIdx.x;
    __shared__ int s_L[NSEQ];
    if (tid == 0) {
        for (int j = 0; j < NSEQ; j++) s_L[j] = j;
        for (int k = NSEQ - 1; k >= 0; k--) {
            int p = g_piv[b * NSEQ + k];
            if (p != k) { int t = s_L[k]; s_L[k] = s_L[p]; s_L[p] = t; }
        }
    }
    __syncthreads();
    g_perm[b * NSEQ + s_L[tid]] = tid;
}

// ---------------- coalesced permuted transpose + diag: BT[Linv[j]][i] = C[i][j] ----------------
__global__ void permT_k() {
    int b = blockIdx.z;
    const float* C = g_W + (size_t)b * NM;
    float* BT = g_BT + (size_t)b * NM;
    const int* Linv = g_perm + b * NSEQ;
    __shared__ float sm[32][33];
    int i0 = blockIdx.y * 32, j0 = blockIdx.x * 32;
    int tx = threadIdx.x, ty = threadIdx.y;
    #pragma unroll
    for (int k = 0; k < 4; k++)
        sm[ty + 8*k][tx] = C[(size_t)(i0 + ty + 8*k) * NSEQ + j0 + tx];
    __syncthreads();
    #pragma unroll
    for (int k = 0; k < 4; k++) {
        int j = j0 + ty + 8*k;
        int lj = Linv[j];
        float v = sm[tx][ty + 8*k];
        BT[(size_t)lj * NSEQ + i0 + tx] = v;
        if (lj == i0 + tx) g_diagB[b * NSEQ + lj] = v;
    }
}

// ---------------- marginals Y (written straight into out) + fp64 dot(Y, scores) ----------------
__global__ void __launch_bounds__(512) y_k(const int* __restrict__ lengths,
                                           const float* __restrict__ scores,
                                           float* __restrict__ Yout) {
    int h = blockIdx.x, b = blockIdx.y, m = threadIdx.x;
    int len = lengths[b];
    float c = dec_f(g_cbits[b]);
    float s = scores[(size_t)b * NM + (size_t)h * NSEQ + m];
    float y = 0.f;
    if (h <= len && m >= 1 && m <= len && h != m) {
        float A = __expf(s - c);
        float diag = (m >= 2) ? g_diagB[b * NSEQ + (m - 1)] : 0.f;
        float G;
        if (h == 0) G = g_BT[(size_t)b * NM + (m - 1)] + diag;   // BT row 0 = Binv[:,0]
        else        G = diag - ((h >= 2) ? g_BT[(size_t)b * NM + (size_t)(h - 1) * NSEQ + (m - 1)] : 0.f);
        y = A * G;
    }
    Yout[(size_t)b * NM + (size_t)h * NSEQ + m] = y;

    float v = y * s;
    #pragma unroll
    for (int o = 16; o; o >>= 1) v += __shfl_down_sync(0xffffffffu, v, o);
    __shared__ float ws[16];
    if ((m & 31) == 0) ws[m >> 5] = v;
    __syncthreads();
    if (m < 16) {
        v = ws[m];
        #pragma unroll
        for (int o = 8; o; o >>= 1) v += __shfl_down_sync(0xffffu, v, o);
        if (m == 0) atomicAdd(&g_dotp[b], (double)v);
    }
}

__global__ void fin_k(const int* __restrict__ lengths, float* __restrict__ out) {
    int b = threadIdx.x;
    if (b < BB) {
        float logZ = (float)g_logdet[b] + (float)lengths[b] * dec_f(g_cbits[b]);
        out[(size_t)BB * NM + b] = logZ;
        out[(size_t)2 * BB * NM + BB + b] = logZ - (float)g_dotp[b];
    }
}

extern "C" void kernel_launch(void* const* d_in, const int* in_sizes, int n_in,
                              void* d_out, int out_size) {
    const float* Xh = (const float*)d_in[0];
    const float* Xm = (const float*)d_in[1];
    const int*   lengths = (const int*)d_in[2];
    const float* Wh = (const float*)d_in[3];
    const float* bh = (const float*)d_in[4];
    const float* Wm = (const float*)d_in[5];
    const float* bm = (const float*)d_in[6];
    const float* V  = (const float*)d_in[7];
    float* out = (float*)d_out;

    void* p;
    cudaGetSymbolAddress(&p, g_H0);     float* pH0 = (float*)p;
    cudaGetSymbolAddress(&p, g_M0);     float* pM0 = (float*)p;
    cudaGetSymbolAddress(&p, g_Hb);     float* pHb = (float*)p;
    cudaGetSymbolAddress(&p, g_Mb);     float* pMb = (float*)p;
    cudaGetSymbolAddress(&p, g_T);      float* pT  = (float*)p;

    float* pSc = out;                               // scores block of output
    float* pY  = out + (size_t)BB * NM + BB;        // Y block of output (16B-aligned)

    dim3 gProj(DH / 64, (BB * NSEQ) / 64, 1);

    gemm_k<false, true, 1><<<gProj, 256>>>(Xh, Wh, bh, pH0, BB*NSEQ, DH, DIN, DIN, DIN, DH, 0, 0, 0);
    gemm_k<false, true, 1><<<gProj, 256>>>(Xm, Wm, bm, pM0, BB*NSEQ, DH, DIN, DIN, DIN, DH, 0, 0, 0);
    relu_k<<<(HS + 255) / 256, 256>>>(pH0, pHb, HS);
    relu_k<<<(HS + 255) / 256, 256>>>(pM0, pMb, HS);

    dim3 gBig128(1, (BB * NSEQ) / 128, 1);        // flattened 16384x128 outputs
    dim3 gScB(NSEQ / 128, NSEQ / 128, BB);        // (4,4,32) batched 512x512
    dim3 gYMB(1, NSEQ / 128, BB);                 // (1,4,32) batched 512x128

    for (int it = 0; it < NITER; it++) {
        float* H = pHb + (size_t)(it & 1) * HS;
        float* M = pMb + (size_t)(it & 1) * HS;
        init_k<<<1, BB>>>();
        // T = H @ V
        gemmBig<false, false, 0, false><<<gBig128, 256>>>(H, V, nullptr, pT, DH, DH, DH, DH, 0, 0, 0, nullptr);
        // scores = T @ M^T (batched) + fused masked max -> straight into out
        gemmBig<false, true, 3, false><<<gScB, 256>>>(pT, M, nullptr, pSc, DH, DH, DH, NSEQ,
                                                      (long)NSEQ*DH, (long)NSEQ*DH, (long)NM, lengths);
        lhat_k<<<dim3(NSEQ, BB), NSEQ>>>(lengths, pSc);
        diagfix_k<<<dim3(16, BB), dim3(32, 32)>>>();
        for (int k0 = 0; k0 < NSEQ; k0 += NB) {
            panel_k<<<BB, 512>>>(k0);
            upd_k<<<dim3(8, 8, BB), 256>>>(k0);
        }
        labels_k<<<BB, 512>>>();
        permT_k<<<dim3(16, 16, BB), dim3(32, 8)>>>();
        y_k<<<dim3(NSEQ, BB), NSEQ>>>(lengths, pSc, pY);

        if (it < NITER - 1) {
            float* Hn = pHb + (size_t)((it + 1) & 1) * HS;
            float* Mn = pMb + (size_t)((it + 1) & 1) * HS;
            // T = Y @ M (batched, len-pruned)
            gemmBig<false, false, 0, true><<<gYMB, 256>>>(pY, M, nullptr, pT, NSEQ, NSEQ, DH, DH,
                                                          (long)NM, (long)NSEQ*DH, (long)NSEQ*DH, lengths);
            // Hn = relu(H0 + T @ V^T)
            gemmBig<false, true, 2, false><<<gBig128, 256>>>(pT, V, pH0, Hn, DH, DH, DH, DH, 0, 0, 0, nullptr);
            // T = Y^T @ H (batched, len-pruned)
            gemmBig<true, false, 0, true><<<gYMB, 256>>>(pY, H, nullptr, pT, NSEQ, NSEQ, DH, DH,
                                                         (long)NM, (long)NSEQ*DH, (long)NSEQ*DH, lengths);
            // Mn = relu(M0 + T @ V)
            gemmBig<false, false, 2, false><<<gBig128, 256>>>(pT, V, pM0, Mn, DH, DH, DH, DH, 0, 0, 0, nullptr);
        }
    }

    fin_k<<<1, BB>>>(lengths, out);
}

// round 15
// speedup vs baseline: 1.0275x; 1.0094x over previous
#include <cuda_runtime.h>
#include <math.h>

#define BB   32
#define NSEQ 512
#define DIN  256
#define DH   128
#define NITER 10
#define NM   (NSEQ*NSEQ)
#define HS   (BB*NSEQ*DH)
#define NB   32

// ---------------- device scratch (no runtime allocation) ----------------
static __device__ float  g_H0[HS];
static __device__ float  g_M0[HS];
static __device__ float  g_Hb[2*HS];
static __device__ float  g_Mb[2*HS];
static __device__ float  g_T[HS];
static __device__ float  g_W[BB*NM];      // Lhat -> in-place GJ result (cols scrambled)
static __device__ float  g_BT[BB*NM];     // BT[j][i] = Binv[i][j]
static __device__ float  g_F[BB*NSEQ*NB]; // panel transform, row-major [512][NB]
static __device__ float  g_Wp[BB*NB*NSEQ];// swapped panel rows [NB][512]
static __device__ unsigned g_cbits[BB];   // order-encoded max
static __device__ float  g_S[BB*NSEQ];    // At row 0 (h=1) values, stashed by lhat
static __device__ double g_logdet[BB];
static __device__ double g_dotp[BB];
static __device__ float  g_diagB[BB*NSEQ];
static __device__ int    g_piv[BB*NSEQ];
static __device__ int    g_perm[BB*NSEQ]; // Linv labels

__device__ __forceinline__ unsigned enc_f(float v) {
    unsigned u = __float_as_uint(v);
    return (u & 0x80000000u) ? ~u : (u | 0x80000000u);
}
__device__ __forceinline__ float dec_f(unsigned k) {
    return (k & 0x80000000u) ? __uint_as_float(k & 0x7fffffffu) : __uint_as_float(~k);
}

// ---- packed fp32x2 FMA (Blackwell double-pumped fp32; PTX-only, ptxas won't emit) ----
__device__ __forceinline__ unsigned long long pack2(float lo, float hi) {
    unsigned long long r;
    asm("mov.b64 %0, {%1, %2};" : "=l"(r) : "f"(lo), "f"(hi));
    return r;
}
__device__ __forceinline__ void fma2(unsigned long long& acc, unsigned long long a, unsigned long long b) {
    asm("fma.rn.f32x2 %0, %1, %2, %0;" : "+l"(acc) : "l"(a), "l"(b));
}
__device__ __forceinline__ float2 unpack2(unsigned long long p) {
    float lo, hi;
    asm("mov.b64 {%0, %1}, %2;" : "=f"(lo), "=f"(hi) : "l"(p));
    return make_float2(lo, hi);
}

// ---------------- 64x64 GEMM (startup projections; optional fused relu copy) ----------------
template<bool TA, bool TB, int EPI, bool RELU2>
__global__ void __launch_bounds__(256) gemm_k(
    const float* __restrict__ A, const float* __restrict__ B,
    const float* __restrict__ C0, float* __restrict__ C, float* __restrict__ C2,
    int M, int N, int K, int lda, int ldb, int ldc,
    long sA, long sB, long sC)
{
    int bz = blockIdx.z;
    A += (long)bz * sA;  B += (long)bz * sB;  C += (long)bz * sC;
    __shared__ float As[16][64];
    __shared__ float Bs[16][64];
    int tid = threadIdx.x;
    int i0 = blockIdx.y * 64, j0 = blockIdx.x * 64;
    int tx = tid & 15, ty = tid >> 4;
    float acc[4][4] = {};
    for (int k0 = 0; k0 < K; k0 += 16) {
        if (!TA) {
            int i = tid >> 2, kk = (tid & 3) << 2;
            float4 v = *(const float4*)(A + (long)(i0 + i) * lda + k0 + kk);
            As[kk + 0][i] = v.x; As[kk + 1][i] = v.y; As[kk + 2][i] = v.z; As[kk + 3][i] = v.w;
        } else {
            int kk = tid >> 4, i4 = (tid & 15) << 2;
            float4 v = *(const float4*)(A + (long)(k0 + kk) * lda + i0 + i4);
            *(float4*)&As[kk][i4] = v;
        }
        if (!TB) {
            int kk = tid >> 4, j4 = (tid & 15) << 2;
            float4 v = *(const float4*)(B + (long)(k0 + kk) * ldb + j0 + j4);
            *(float4*)&Bs[kk][j4] = v;
        } else {
            int j = tid >> 2, kk = (tid & 3) << 2;
            float4 v = *(const float4*)(B + (long)(j0 + j) * ldb + k0 + kk);
            Bs[kk + 0][j] = v.x; Bs[kk + 1][j] = v.y; Bs[kk + 2][j] = v.z; Bs[kk + 3][j] = v.w;
        }
        __syncthreads();
        #pragma unroll
        for (int kk = 0; kk < 16; kk++) {
            float4 av = *(const float4*)&As[kk][ty << 2];
            float4 bv = *(const float4*)&Bs[kk][tx << 2];
            float ar[4] = {av.x, av.y, av.z, av.w};
            float br[4] = {bv.x, bv.y, bv.z, bv.w};
            #pragma unroll
            for (int a = 0; a < 4; a++)
                #pragma unroll
                for (int q = 0; q < 4; q++)
                    acc[a][q] = fmaf(ar[a], br[q], acc[a][q]);
        }
        __syncthreads();
    }
    #pragma unroll
    for (int a = 0; a < 4; a++) {
        int row = i0 + (ty << 2) + a;
        long off = (long)row * ldc + j0 + (tx << 2);
        float4 r = make_float4(acc[a][0], acc[a][1], acc[a][2], acc[a][3]);
        if (EPI == 1) {
            float4 bb = *(const float4*)(C0 + j0 + (tx << 2));
            r.x += bb.x; r.y += bb.y; r.z += bb.z; r.w += bb.w;
        }
        *(float4*)(C + off) = r;
        if (RELU2) {
            float4 rr = make_float4(fmaxf(r.x, 0.f), fmaxf(r.y, 0.f), fmaxf(r.z, 0.f), fmaxf(r.w, 0.f));
            *(float4*)(C2 + off) = rr;
        }
    }
}

// ---------------- 128x128 GEMM, 8x8 micro, 256 threads, packed f32x2 FMA ----------------
// EPI: 0 plain, 2 relu(C0+acc), 3 store + fused masked atomic max.
// LENA: exact len-pruning for Y-operand GEMMs. INIT0: CTA (0, y=0) zeroes cbits/dotp.
template<bool TA, bool TB, int EPI, bool LENA, bool INIT0>
__global__ void __launch_bounds__(256) gemmBig(
    const float* __restrict__ A, const float* __restrict__ B,
    const float* __restrict__ C0, float* __restrict__ C,
    int K, int lda, int ldb, int ldc,
    long sA, long sB, long sC,
    const int* __restrict__ lengths)
{
    int bz = blockIdx.z;
    int tid = threadIdx.x;
    if (INIT0) {
        if (blockIdx.y == 0 && blockIdx.x == 0 && bz == 0 && tid < BB) {
            g_cbits[tid] = 0u; g_dotp[tid] = 0.0;
        }
    }
    A += (long)bz * sA;  B += (long)bz * sB;  C += (long)bz * sC;
    __shared__ float As[16][128];
    __shared__ float Bs[16][128];
    int i0 = blockIdx.y * 128, j0 = blockIdx.x * 128;
    int ty = tid >> 4, tx = tid & 15;
    int rbase = ty << 3, cbase = tx << 3;

    int Kend = K;
    int len = 0;
    if (LENA || EPI == 3) len = lengths[bz];
    if (LENA) {
        if (i0 > len) {
            #pragma unroll
            for (int a = 0; a < 8; a++) {
                long off = (long)(i0 + rbase + a) * ldc + j0 + cbase;
                *(float4*)(C + off)     = make_float4(0.f, 0.f, 0.f, 0.f);
                *(float4*)(C + off + 4) = make_float4(0.f, 0.f, 0.f, 0.f);
            }
            return;
        }
        Kend = min(K, (len + 16) & ~15);
    }

    unsigned long long acc2[8][4] = {};   // 8 rows x 4 col-pairs (packed fp32x2)
    for (int k0 = 0; k0 < Kend; k0 += 16) {
        if (!TA) {
            int i = tid >> 1, kb = (tid & 1) << 3;
            float4 v1 = *(const float4*)(A + (long)(i0 + i) * lda + k0 + kb);
            float4 v2 = *(const float4*)(A + (long)(i0 + i) * lda + k0 + kb + 4);
            As[kb+0][i] = v1.x; As[kb+1][i] = v1.y; As[kb+2][i] = v1.z; As[kb+3][i] = v1.w;
            As[kb+4][i] = v2.x; As[kb+5][i] = v2.y; As[kb+6][i] = v2.z; As[kb+7][i] = v2.w;
        } else {
            int kk = tid >> 4, i8 = (tid & 15) << 3;
            *(float4*)&As[kk][i8]     = *(const float4*)(A + (long)(k0 + kk) * lda + i0 + i8);
            *(float4*)&As[kk][i8 + 4] = *(const float4*)(A + (long)(k0 + kk) * lda + i0 + i8 + 4);
        }
        if (!TB) {
            int kk = tid >> 4, j8 = (tid & 15) << 3;
            *(float4*)&Bs[kk][j8]     = *(const float4*)(B + (long)(k0 + kk) * ldb + j0 + j8);
            *(float4*)&Bs[kk][j8 + 4] = *(const float4*)(B + (long)(k0 + kk) * ldb + j0 + j8 + 4);
        } else {
            int j = tid >> 1, kb = (tid & 1) << 3;
            float4 v1 = *(const float4*)(B + (long)(j0 + j) * ldb + k0 + kb);
            float4 v2 = *(const float4*)(B + (long)(j0 + j) * ldb + k0 + kb + 4);
            Bs[kb+0][j] = v1.x; Bs[kb+1][j] = v1.y; Bs[kb+2][j] = v1.z; Bs[kb+3][j] = v1.w;
            Bs[kb+4][j] = v2.x; Bs[kb+5][j] = v2.y; Bs[kb+6][j] = v2.z; Bs[kb+7][j] = v2.w;
        }
        __syncthreads();
        #pragma unroll
        for (int kk = 0; kk < 16; kk++) {
            float4 a1 = *(const float4*)&As[kk][rbase];
            float4 a2 = *(const float4*)&As[kk][rbase + 4];
            float4 b1 = *(const float4*)&Bs[kk][cbase];
            float4 b2 = *(const float4*)&Bs[kk][cbase + 4];
            unsigned long long bp0 = pack2(b1.x, b1.y);
            unsigned long long bp1 = pack2(b1.z, b1.w);
            unsigned long long bp2 = pack2(b2.x, b2.y);
            unsigned long long bp3 = pack2(b2.z, b2.w);
            float ar[8] = {a1.x, a1.y, a1.z, a1.w, a2.x, a2.y, a2.z, a2.w};
            #pragma unroll
            for (int a = 0; a < 8; a++) {
                unsigned long long ap = pack2(ar[a], ar[a]);
                fma2(acc2[a][0], ap, bp0);
                fma2(acc2[a][1], ap, bp1);
                fma2(acc2[a][2], ap, bp2);
                fma2(acc2[a][3], ap, bp3);
            }
        }
        __syncthreads();
    }

    unsigned key = 0u;
    #pragma unroll
    for (int a = 0; a < 8; a++) {
        int row = i0 + rbase + a;
        long off = (long)row * ldc + j0 + cbase;
        float2 p0 = unpack2(acc2[a][0]);
        float2 p1 = unpack2(acc2[a][1]);
        float2 p2 = unpack2(acc2[a][2]);
        float2 p3 = unpack2(acc2[a][3]);
        float4 r1 = make_float4(p0.x, p0.y, p1.x, p1.y);
        float4 r2 = make_float4(p2.x, p2.y, p3.x, p3.y);
        if (EPI == 2) {
            float4 c1 = *(const float4*)(C0 + off);
            float4 c2 = *(const float4*)(C0 + off + 4);
            r1.x = fmaxf(c1.x + r1.x, 0.f); r1.y = fmaxf(c1.y + r1.y, 0.f);
            r1.z = fmaxf(c1.z + r1.z, 0.f); r1.w = fmaxf(c1.w + r1.w, 0.f);
            r2.x = fmaxf(c2.x + r2.x, 0.f); r2.y = fmaxf(c2.y + r2.y, 0.f);
            r2.z = fmaxf(c2.z + r2.z, 0.f); r2.w = fmaxf(c2.w + r2.w, 0.f);
        }
        *(float4*)(C + off)     = r1;
        *(float4*)(C + off + 4) = r2;
        if (EPI == 3) {
            int h = row;
            float vals[8] = {r1.x, r1.y, r1.z, r1.w, r2.x, r2.y, r2.z, r2.w};
            #pragma unroll
            for (int q = 0; q < 8; q++) {
                int m = j0 + cbase + q;
                if (h <= len && m >= 1 && m <= len && h != m) {
                    unsigned k2 = enc_f(vals[q]);
                    if (k2 > key) key = k2;
                }
            }
        }
    }
    if (EPI == 3) {
        #pragma unroll
        for (int o = 16; o; o >>= 1) {
            unsigned ok = __shfl_down_sync(0xffffffffu, key, o);
            if (ok > key) key = ok;
        }
        if ((tid & 31) == 0 && key) atomicMax(&g_cbits[bz], key);
    }
}

// ---------------- build padded 512x512 Lhat; i==0 CTA stashes At row 0 into g_S ----------------
__global__ void lhat_k(const int* __restrict__ lengths, const float* __restrict__ scores) {
    int i = blockIdx.x, b = blockIdx.y, j = threadIdx.x, len = lengths[b];
    float c = dec_f(g_cbits[b]);
    const float* sc = scores + (size_t)b * NM;
    float v;
    if (i == NSEQ - 1)      v = (j == NSEQ - 1) ? 1.f : 0.f;
    else if (j == NSEQ - 1) v = 0.f;
    else if (i == 0) {
        int m = j + 1;
        v = (m <= len) ? __expf(sc[m] - c) : 0.f;   // r[j]
        float r1 = (m <= len && m != 1) ? __expf(sc[NSEQ + m] - c) : 0.f;
        g_S[b * NSEQ + j] = r1;
    }
    else if (j == i) {
        int m = i + 1;
        float r = (m <= len) ? __expf(sc[m] - c) : 0.f;
        v = r + ((m <= len) ? 0.f : 1.f);           // S added later by diagfix_k
    } else {
        int h = i + 1, m = j + 1;
        v = (h <= len && m <= len) ? -__expf(sc[h * NSEQ + m] - c) : 0.f;
    }
    g_W[(size_t)b * NM + (size_t)i * NSEQ + j] = v;
}

// ---------------- diag += S, with S_j = row1[j] - sum_{h in [1,510], h!=j} W[h][j] ----------------
__global__ void __launch_bounds__(1024) diagfix_k() {
    int b = blockIdx.y;
    int x = threadIdx.x, y = threadIdx.y;   // (32,32)
    int j = blockIdx.x * 32 + x;
    float* W = g_W + (size_t)b * NM;
    float part = 0.f;
    for (int h = 1 + y; h < NSEQ - 1; h += 32)
        if (h != j) part += W[(size_t)h * NSEQ + j];
    __shared__ float red[32][33];
    red[y][x] = part;
    __syncthreads();
    if (y == 0 && j >= 1 && j <= NSEQ - 2) {
        float s = 0.f;
        #pragma unroll
        for (int k = 0; k < 32; k++) s += red[k][x];
        float S = g_S[b * NSEQ + j] - s;
        W[(size_t)j * NSEQ + j] += S;
    }
}

// ---------------- panel factor: 512xNB panel, one row per thread, in registers ----------------
__global__ void __launch_bounds__(512) panel_k(int k0) {
    int b = blockIdx.x, tid = threadIdx.x;
    float* W = g_W + (size_t)b * NM;
    float a[NB];
    {
        const float4* src = (const float4*)(W + (size_t)tid * NSEQ + k0);
        #pragma unroll
        for (int q = 0; q < NB/4; q++) {
            float4 v = src[q];
            a[4*q] = v.x; a[4*q+1] = v.y; a[4*q+2] = v.z; a[4*q+3] = v.w;
        }
    }
    __shared__ float s_tmpK[NB], s_tmpP[NB];
    __shared__ float red_v[16]; __shared__ int red_i[16];
    __shared__ int sh_p;
    __shared__ int s_pivloc[NB];
    __shared__ double sh_ld;
    __shared__ int s_src[NSEQ];
    __shared__ int s_aff[64];
    __shared__ int s_cnt;
    if (tid == 0) { sh_ld = (k0 == 0) ? 0.0 : g_logdet[b]; s_cnt = 0; }
    s_src[tid] = tid;

    #pragma unroll
    for (int j = 0; j < NB; j++) {
        int k = k0 + j;
        float best = (tid >= k) ? fabsf(a[j]) : -1.f;
        int bi = tid;
        #pragma unroll
        for (int o = 16; o; o >>= 1) {
            float ov = __shfl_down_sync(0xffffffffu, best, o);
            int   oi = __shfl_down_sync(0xffffffffu, bi, o);
            if (ov > best) { best = ov; bi = oi; }
        }
        if ((tid & 31) == 0) { red_v[tid >> 5] = best; red_i[tid >> 5] = bi; }
        __syncthreads();
        if (tid < 32) {
            best = (tid < 16) ? red_v[tid] : -2.f;
            bi   = (tid < 16) ? red_i[tid] : 0;
            #pragma unroll
            for (int o = 8; o; o >>= 1) {
                float ov = __shfl_down_sync(0xffffffffu, best, o);
                int   oi = __shfl_down_sync(0xffffffffu, bi, o);
                if (ov > best) { best = ov; bi = oi; }
            }
            if (tid == 0) { sh_p = bi; s_pivloc[j] = bi; }
        }
        __syncthreads();
        int p = sh_p;
        if (tid == k) {
            for (int jj = 0; jj < NB; jj++) s_tmpK[jj] = a[jj];
        }
        if (tid == p) {
            for (int jj = 0; jj < NB; jj++) s_tmpP[jj] = a[jj];
        }
        __syncthreads();
        const float* prow = (p != k) ? s_tmpP : s_tmpK;
        if (p != k) {
            if (tid == k) {
                for (int jj = 0; jj < NB; jj++) a[jj] = s_tmpP[jj];
            }
            if (tid == p) {
                for (int jj = 0; jj < NB; jj++) a[jj] = s_tmpK[jj];
            }
        }
        float piv = prow[j];
        float pivinv = 1.f / piv;
        if (tid == 0) sh_ld += log(fabs((double)piv));
        if (tid == k) {
            #pragma unroll
            for (int jj = 0; jj < NB; jj++) a[jj] = (jj == j) ? pivinv : prow[jj] * pivinv;
        } else {
            float cm = a[j];
            #pragma unroll
            for (int jj = 0; jj < NB; jj++)
                if (jj != j) a[jj] = fmaf(-cm, prow[jj] * pivinv, a[jj]);
            a[j] = -cm * pivinv;
        }
        __syncthreads();
    }

    {
        float4* fd = (float4*)(g_F + ((size_t)b * NSEQ + tid) * NB);
        #pragma unroll
        for (int q = 0; q < NB/4; q++)
            fd[q] = make_float4(a[4*q], a[4*q+1], a[4*q+2], a[4*q+3]);
    }

    if (tid == 0) {
        for (int j = 0; j < NB; j++) {
            int k = k0 + j, p = s_pivloc[j];
            if (p != k) { int t = s_src[k]; s_src[k] = s_src[p]; s_src[p] = t; }
        }
    }
    __syncthreads();
    if (s_src[tid] != tid) { int idx = atomicAdd(&s_cnt, 1); s_aff[idx] = tid; }
    __syncthreads();
    int cnt = s_cnt;
    {
        float buf[64];
        #pragma unroll
        for (int aa = 0; aa < 64; aa++)
            if (aa < cnt) buf[aa] = W[(size_t)s_src[s_aff[aa]] * NSEQ + tid];
        #pragma unroll
        for (int aa = 0; aa < 64; aa++)
            if (aa < cnt) W[(size_t)s_aff[aa] * NSEQ + tid] = buf[aa];
    }
    __syncthreads();

    for (int t = tid; t < NB * NSEQ; t += 512) {
        int r = t >> 9, c4 = t & 511;
        g_Wp[(size_t)b * NB * NSEQ + t] = W[(size_t)(k0 + r) * NSEQ + c4];
    }
    {
        float4* wd = (float4*)(W + (size_t)tid * NSEQ + k0);
        #pragma unroll
        for (int q = 0; q < NB/4; q++)
            wd[q] = make_float4(a[4*q], a[4*q+1], a[4*q+2], a[4*q+3]);
    }
    if (tid < NB) g_piv[b * NSEQ + k0 + tid] = s_pivloc[tid];
    if (tid == 0) g_logdet[b] = sh_ld;
}

// ---------------- rank-NB trailing update: W = base + F*Wp, full chip, f32x2 ----------------
__global__ void __launch_bounds__(256) upd_k(int k0) {
    int b = blockIdx.z;
    float* W = g_W + (size_t)b * NM;
    const float* F  = g_F  + (size_t)b * NSEQ * NB;
    const float* Wp = g_Wp + (size_t)b * NB * NSEQ;
    __shared__ float Fs[NB][64];
    __shared__ float Bs[NB][64];
    int tid = threadIdx.x;
    int i0 = blockIdx.y * 64, j0 = blockIdx.x * 64;
    {
        int i = tid >> 2, kk = (tid & 3) << 3;
        float4 v1 = *(const float4*)(F + (size_t)(i0 + i) * NB + kk);
        float4 v2 = *(const float4*)(F + (size_t)(i0 + i) * NB + kk + 4);
        Fs[kk+0][i] = v1.x; Fs[kk+1][i] = v1.y; Fs[kk+2][i] = v1.z; Fs[kk+3][i] = v1.w;
        Fs[kk+4][i] = v2.x; Fs[kk+5][i] = v2.y; Fs[kk+6][i] = v2.z; Fs[kk+7][i] = v2.w;
    }
    {
        int kk = tid >> 3, j8 = (tid & 7) << 3;
        *(float4*)&Bs[kk][j8]     = *(const float4*)(Wp + (size_t)kk * NSEQ + j0 + j8);
        *(float4*)&Bs[kk][j8 + 4] = *(const float4*)(Wp + (size_t)kk * NSEQ + j0 + j8 + 4);
    }
    __syncthreads();
    int tx = tid & 15, ty = tid >> 4;
    unsigned long long acc2[4][2] = {};
    #pragma unroll
    for (int kk = 0; kk < NB; kk++) {
        float4 av = *(const float4*)&Fs[kk][ty << 2];
        float4 bv = *(const float4*)&Bs[kk][tx << 2];
        unsigned long long bp0 = pack2(bv.x, bv.y);
        unsigned long long bp1 = pack2(bv.z, bv.w);
        float ar[4] = {av.x, av.y, av.z, av.w};
        #pragma unroll
        for (int a = 0; a < 4; a++) {
            unsigned long long ap = pack2(ar[a], ar[a]);
            fma2(acc2[a][0], ap, bp0);
            fma2(acc2[a][1], ap, bp1);
        }
    }
    int col = j0 + (tx << 2);
    bool pcol = (col >= k0 && col < k0 + NB);
    if (pcol) return;
    #pragma unroll
    for (int a = 0; a < 4; a++) {
        int row = i0 + (ty << 2) + a;
        bool prow = (row >= k0 && row < k0 + NB);
        float4* wp4 = (float4*)(W + (size_t)row * NSEQ + col);
        float2 p0 = unpack2(acc2[a][0]);
        float2 p1 = unpack2(acc2[a][1]);
        float4 r = make_float4(p0.x, p0.y, p1.x, p1.y);
        if (!prow) {
            float4 base = *wp4;
            r.x += base.x; r.y += base.y; r.z += base.z; r.w += base.w;
        }
        *wp4 = r;
    }
}

// ---------------- resolve labels: g_perm = Linv (Linv[L[j]] = j) ----------------
__global__ void __launch_bounds__(512) labels_k() {
    int b = blockIdx.x, tid = threadIdx.x;
    __shared__ int s_L[NSEQ];
    if (tid == 0) {
        for (int j = 0; j < NSEQ; j++) s_L[j] = j;
        for (int k = NSEQ - 1; k >= 0; k--) {
            int p = g_piv[b * NSEQ + k];
            if (p != k) { int t = s_L[k]; s_L[k] = s_L[p]; s_L[p] = t; }
        }
    }
    __syncthreads();
    g_perm[b * NSEQ + s_L[tid]] = tid;
}

// ---------------- coalesced permuted transpose + diag: BT[Linv[j]][i] = C[i][j] ----------------
__global__ void permT_k() {
    int b = blockIdx.z;
    const float* C = g_W + (size_t)b * NM;
    float* BT = g_BT + (size_t)b * NM;
    const int* Linv = g_perm + b * NSEQ;
    __shared__ float sm[32][33];
    int i0 = blockIdx.y * 32, j0 = blockIdx.x * 32;
    int tx = threadIdx.x, ty = threadIdx.y;
    #pragma unroll
    for (int k = 0; k < 4; k++)
        sm[ty + 8*k][tx] = C[(size_t)(i0 + ty + 8*k) * NSEQ + j0 + tx];
    __syncthreads();
    #pragma unroll
    for (int k = 0; k < 4; k++) {
        int j = j0 + ty + 8*k;
        int lj = Linv[j];
        float v = sm[tx][ty + 8*k];
        BT[(size_t)lj * NSEQ + i0 + tx] = v;
        if (lj == i0 + tx) g_diagB[b * NSEQ + lj] = v;
    }
}

// ---------------- marginals Y (straight into out) + fp64 dot(Y, scores) ----------------
__global__ void __launch_bounds__(512) y_k(const int* __restrict__ lengths,
                                           const float* __restrict__ scores,
                                           float* __restrict__ Yout) {
    int h = blockIdx.x, b = blockIdx.y, m = threadIdx.x;
    int len = lengths[b];
    float c = dec_f(g_cbits[b]);
    float s = scores[(size_t)b * NM + (size_t)h * NSEQ + m];
    float y = 0.f;
    if (h <= len && m >= 1 && m <= len && h != m) {
        float A = __expf(s - c);
        float diag = (m >= 2) ? g_diagB[b * NSEQ + (m - 1)] : 0.f;
        float G;
        if (h == 0) G = g_BT[(size_t)b * NM + (m - 1)] + diag;
        else        G = diag - ((h >= 2) ? g_BT[(size_t)b * NM + (size_t)(h - 1) * NSEQ + (m - 1)] : 0.f);
        y = A * G;
    }
    Yout[(size_t)b * NM + (size_t)h * NSEQ + m] = y;

    float v = y * s;
    #pragma unroll
    for (int o = 16; o; o >>= 1) v += __shfl_down_sync(0xffffffffu, v, o);
    __shared__ float ws[16];
    if ((m & 31) == 0) ws[m >> 5] = v;
    __syncthreads();
    if (m < 16) {
        v = ws[m];
        #pragma unroll
        for (int o = 8; o; o >>= 1) v += __shfl_down_sync(0xffffu, v, o);
        if (m == 0) atomicAdd(&g_dotp[b], (double)v);
    }
}

__global__ void fin_k(const int* __restrict__ lengths, float* __restrict__ out) {
    int b = threadIdx.x;
    if (b < BB) {
        float logZ = (float)g_logdet[b] + (float)lengths[b] * dec_f(g_cbits[b]);
        out[(size_t)BB * NM + b] = logZ;
        out[(size_t)2 * BB * NM + BB + b] = logZ - (float)g_dotp[b];
    }
}

extern "C" void kernel_launch(void* const* d_in, const int* in_sizes, int n_in,
                              void* d_out, int out_size) {
    const float* Xh = (const float*)d_in[0];
    const float* Xm = (const float*)d_in[1];
    const int*   lengths = (const int*)d_in[2];
    const float* Wh = (const float*)d_in[3];
    const float* bh = (const float*)d_in[4];
    const float* Wm = (const float*)d_in[5];
    const float* bm = (const float*)d_in[6];
    const float* V  = (const float*)d_in[7];
    float* out = (float*)d_out;

    void* p;
    cudaGetSymbolAddress(&p, g_H0);     float* pH0 = (float*)p;
    cudaGetSymbolAddress(&p, g_M0);     float* pM0 = (float*)p;
    cudaGetSymbolAddress(&p, g_Hb);     float* pHb = (float*)p;
    cudaGetSymbolAddress(&p, g_Mb);     float* pMb = (float*)p;
    cudaGetSymbolAddress(&p, g_T);      float* pT  = (float*)p;

    float* pSc = out;                               // scores block of output
    float* pY  = out + (size_t)BB * NM + BB;        // Y block of output (16B-aligned)

    dim3 gProj(DH / 64, (BB * NSEQ) / 64, 1);

    // startup projections with fused relu copy (H0 raw + relu -> Hb[0])
    gemm_k<false, true, 1, true><<<gProj, 256>>>(Xh, Wh, bh, pH0, pHb, BB*NSEQ, DH, DIN, DIN, DIN, DH, 0, 0, 0);
    gemm_k<false, true, 1, true><<<gProj, 256>>>(Xm, Wm, bm, pM0, pMb, BB*NSEQ, DH, DIN, DIN, DIN, DH, 0, 0, 0);

    dim3 gBig128(1, (BB * NSEQ) / 128, 1);        // flattened 16384x128 outputs
    dim3 gScB(NSEQ / 128, NSEQ / 128, BB);        // (4,4,32) batched 512x512
    dim3 gYMB(1, NSEQ / 128, BB);                 // (1,4,32) batched 512x128

    for (int it = 0; it < NITER; it++) {
        float* H = pHb + (size_t)(it & 1) * HS;
        float* M = pMb + (size_t)(it & 1) * HS;
        // T = H @ V   (also zeroes cbits/dotp in CTA(0,0))
        gemmBig<false, false, 0, false, true><<<gBig128, 256>>>(H, V, nullptr, pT, DH, DH, DH, DH, 0, 0, 0, nullptr);
        // scores = T @ M^T (batched) + fused masked max -> straight into out
        gemmBig<false, true, 3, false, false><<<gScB, 256>>>(pT, M, nullptr, pSc, DH, DH, DH, NSEQ,
                                                             (long)NSEQ*DH, (long)NSEQ*DH, (long)NM, lengths);
        lhat_k<<<dim3(NSEQ, BB), NSEQ>>>(lengths, pSc);
        diagfix_k<<<dim3(16, BB), dim3(32, 32)>>>();
        for (int k0 = 0; k0 < NSEQ; k0 += NB) {
            panel_k<<<BB, 512>>>(k0);
            upd_k<<<dim3(8, 8, BB), 256>>>(k0);
        }
        labels_k<<<BB, 512>>>();
        permT_k<<<dim3(16, 16, BB), dim3(32, 8)>>>();
        y_k<<<dim3(NSEQ, BB), NSEQ>>>(lengths, pSc, pY);

        if (it < NITER - 1) {
            float* Hn = pHb + (size_t)((it + 1) & 1) * HS;
            float* Mn = pMb + (size_t)((it + 1) & 1) * HS;
            // T = Y @ M (batched, len-pruned)
            gemmBig<false, false, 0, true, false><<<gYMB, 256>>>(pY, M, nullptr, pT, NSEQ, NSEQ, DH, DH,
                                                                 (long)NM, (long)NSEQ*DH, (long)NSEQ*DH, lengths);
            // Hn = relu(H0 + T @ V^T)
            gemmBig<false, true, 2, false, false><<<gBig128, 256>>>(pT, V, pH0, Hn, DH, DH, DH, DH, 0, 0, 0, nullptr);
            // T = Y^T @ H (batched, len-pruned)
            gemmBig<true, false, 0, true, false><<<gYMB, 256>>>(pY, H, nullptr, pT, NSEQ, NSEQ, DH, DH,
                                                                (long)NM, (long)NSEQ*DH, (long)NSEQ*DH, lengths);
            // Mn = relu(M0 + T @ V)
            gemmBig<false, false, 2, false, false><<<gBig128, 256>>>(pT, V, pM0, Mn, DH, DH, DH, DH, 0, 0, 0, nullptr);
        }
    }

    fin_k<<<1, BB>>>(lengths, out);
}

// round 16
// speedup vs baseline: 1.2252x; 1.1925x over previous
#include <cuda_runtime.h>
#include <math.h>

#define BB   32
#define NSEQ 512
#define DIN  256
#define DH   128
#define NITER 10
#define NM   (NSEQ*NSEQ)
#define HS   (BB*NSEQ*DH)
#define NB   32

// ---------------- device scratch (no runtime allocation) ----------------
static __device__ float  g_H0[HS];
static __device__ float  g_M0[HS];
static __device__ float  g_Hb[2*HS];
static __device__ float  g_Mb[2*HS];
static __device__ float  g_T[HS];
static __device__ float  g_W[BB*NM];      // Lhat -> in-place GJ result (cols scrambled)
static __device__ float  g_BT[BB*NM];     // BT[j][i] = Binv[i][j]
static __device__ float  g_A[BB*NM];      // A[h][m] = exp(s-c) cache (written by lhat)
static __device__ float  g_F[BB*NSEQ*NB]; // panel transform, row-major [512][NB]
static __device__ float  g_Wp[BB*NB*NSEQ];// swapped panel rows [NB][512]
static __device__ unsigned g_cbits[BB];   // order-encoded max
static __device__ float  g_S[BB*NSEQ];    // At row 0 (h=1) values, stashed by lhat
static __device__ double g_logdet[BB];
static __device__ double g_dotp[BB];
static __device__ float  g_diagB[BB*NSEQ];
static __device__ int    g_piv[BB*NSEQ];
static __device__ int    g_perm[BB*NSEQ]; // Linv labels

__device__ __forceinline__ unsigned enc_f(float v) {
    unsigned u = __float_as_uint(v);
    return (u & 0x80000000u) ? ~u : (u | 0x80000000u);
}
__device__ __forceinline__ float dec_f(unsigned k) {
    return (k & 0x80000000u) ? __uint_as_float(k & 0x7fffffffu) : __uint_as_float(~k);
}

// ---- packed fp32x2 FMA (Blackwell double-pumped fp32; PTX-only) ----
__device__ __forceinline__ unsigned long long pack2(float lo, float hi) {
    unsigned long long r;
    asm("mov.b64 %0, {%1, %2};" : "=l"(r) : "f"(lo), "f"(hi));
    return r;
}
__device__ __forceinline__ void fma2(unsigned long long& acc, unsigned long long a, unsigned long long b) {
    asm("fma.rn.f32x2 %0, %1, %2, %0;" : "+l"(acc) : "l"(a), "l"(b));
}
__device__ __forceinline__ float2 unpack2(unsigned long long p) {
    float lo, hi;
    asm("mov.b64 {%0, %1}, %2;" : "=f"(lo), "=f"(hi) : "l"(p));
    return make_float2(lo, hi);
}

// ---------------- 64x64 GEMM (startup projections; fused relu copy) ----------------
template<bool TA, bool TB, int EPI, bool RELU2>
__global__ void __launch_bounds__(256) gemm_k(
    const float* __restrict__ A, const float* __restrict__ B,
    const float* __restrict__ C0, float* __restrict__ C, float* __restrict__ C2,
    int M, int N, int K, int lda, int ldb, int ldc,
    long sA, long sB, long sC)
{
    int bz = blockIdx.z;
    A += (long)bz * sA;  B += (long)bz * sB;  C += (long)bz * sC;
    __shared__ float As[16][64];
    __shared__ float Bs[16][64];
    int tid = threadIdx.x;
    int i0 = blockIdx.y * 64, j0 = blockIdx.x * 64;
    int tx = tid & 15, ty = tid >> 4;
    float acc[4][4] = {};
    for (int k0 = 0; k0 < K; k0 += 16) {
        if (!TA) {
            int i = tid >> 2, kk = (tid & 3) << 2;
            float4 v = *(const float4*)(A + (long)(i0 + i) * lda + k0 + kk);
            As[kk + 0][i] = v.x; As[kk + 1][i] = v.y; As[kk + 2][i] = v.z; As[kk + 3][i] = v.w;
        } else {
            int kk = tid >> 4, i4 = (tid & 15) << 2;
            float4 v = *(const float4*)(A + (long)(k0 + kk) * lda + i0 + i4);
            *(float4*)&As[kk][i4] = v;
        }
        if (!TB) {
            int kk = tid >> 4, j4 = (tid & 15) << 2;
            float4 v = *(const float4*)(B + (long)(k0 + kk) * ldb + j0 + j4);
            *(float4*)&Bs[kk][j4] = v;
        } else {
            int j = tid >> 2, kk = (tid & 3) << 2;
            float4 v = *(const float4*)(B + (long)(j0 + j) * ldb + k0 + kk);
            Bs[kk + 0][j] = v.x; Bs[kk + 1][j] = v.y; Bs[kk + 2][j] = v.z; Bs[kk + 3][j] = v.w;
        }
        __syncthreads();
        #pragma unroll
        for (int kk = 0; kk < 16; kk++) {
            float4 av = *(const float4*)&As[kk][ty << 2];
            float4 bv = *(const float4*)&Bs[kk][tx << 2];
            float ar[4] = {av.x, av.y, av.z, av.w};
            float br[4] = {bv.x, bv.y, bv.z, bv.w};
            #pragma unroll
            for (int a = 0; a < 4; a++)
                #pragma unroll
                for (int q = 0; q < 4; q++)
                    acc[a][q] = fmaf(ar[a], br[q], acc[a][q]);
        }
        __syncthreads();
    }
    #pragma unroll
    for (int a = 0; a < 4; a++) {
        int row = i0 + (ty << 2) + a;
        long off = (long)row * ldc + j0 + (tx << 2);
        float4 r = make_float4(acc[a][0], acc[a][1], acc[a][2], acc[a][3]);
        if (EPI == 1) {
            float4 bb = *(const float4*)(C0 + j0 + (tx << 2));
            r.x += bb.x; r.y += bb.y; r.z += bb.z; r.w += bb.w;
        }
        *(float4*)(C + off) = r;
        if (RELU2) {
            float4 rr = make_float4(fmaxf(r.x, 0.f), fmaxf(r.y, 0.f), fmaxf(r.z, 0.f), fmaxf(r.w, 0.f));
            *(float4*)(C2 + off) = rr;
        }
    }
}

// ---------------- 128x128 GEMM, 8x8 micro, 256 threads, packed f32x2 FMA ----------------
template<bool TA, bool TB, int EPI, bool LENA, bool INIT0>
__global__ void __launch_bounds__(256) gemmBig(
    const float* __restrict__ A, const float* __restrict__ B,
    const float* __restrict__ C0, float* __restrict__ C,
    int K, int lda, int ldb, int ldc,
    long sA, long sB, long sC,
    const int* __restrict__ lengths)
{
    int bz = blockIdx.z;
    int tid = threadIdx.x;
    if (INIT0) {
        if (blockIdx.y == 0 && blockIdx.x == 0 && bz == 0 && tid < BB) {
            g_cbits[tid] = 0u; g_dotp[tid] = 0.0;
        }
    }
    A += (long)bz * sA;  B += (long)bz * sB;  C += (long)bz * sC;
    __shared__ float As[16][128];
    __shared__ float Bs[16][128];
    int i0 = blockIdx.y * 128, j0 = blockIdx.x * 128;
    int ty = tid >> 4, tx = tid & 15;
    int rbase = ty << 3, cbase = tx << 3;

    int Kend = K;
    int len = 0;
    if (LENA || EPI == 3) len = lengths[bz];
    if (LENA) {
        if (i0 > len) {
            #pragma unroll
            for (int a = 0; a < 8; a++) {
                long off = (long)(i0 + rbase + a) * ldc + j0 + cbase;
                *(float4*)(C + off)     = make_float4(0.f, 0.f, 0.f, 0.f);
                *(float4*)(C + off + 4) = make_float4(0.f, 0.f, 0.f, 0.f);
            }
            return;
        }
        Kend = min(K, (len + 16) & ~15);
    }

    unsigned long long acc2[8][4] = {};
    for (int k0 = 0; k0 < Kend; k0 += 16) {
        if (!TA) {
            int i = tid >> 1, kb = (tid & 1) << 3;
            float4 v1 = *(const float4*)(A + (long)(i0 + i) * lda + k0 + kb);
            float4 v2 = *(const float4*)(A + (long)(i0 + i) * lda + k0 + kb + 4);
            As[kb+0][i] = v1.x; As[kb+1][i] = v1.y; As[kb+2][i] = v1.z; As[kb+3][i] = v1.w;
            As[kb+4][i] = v2.x; As[kb+5][i] = v2.y; As[kb+6][i] = v2.z; As[kb+7][i] = v2.w;
        } else {
            int kk = tid >> 4, i8 = (tid & 15) << 3;
            *(float4*)&As[kk][i8]     = *(const float4*)(A + (long)(k0 + kk) * lda + i0 + i8);
            *(float4*)&As[kk][i8 + 4] = *(const float4*)(A + (long)(k0 + kk) * lda + i0 + i8 + 4);
        }
        if (!TB) {
            int kk = tid >> 4, j8 = (tid & 15) << 3;
            *(float4*)&Bs[kk][j8]     = *(const float4*)(B + (long)(k0 + kk) * ldb + j0 + j8);
            *(float4*)&Bs[kk][j8 + 4] = *(const float4*)(B + (long)(k0 + kk) * ldb + j0 + j8 + 4);
        } else {
            int j = tid >> 1, kb = (tid & 1) << 3;
            float4 v1 = *(const float4*)(B + (long)(j0 + j) * ldb + k0 + kb);
            float4 v2 = *(const float4*)(B + (long)(j0 + j) * ldb + k0 + kb + 4);
            Bs[kb+0][j] = v1.x; Bs[kb+1][j] = v1.y; Bs[kb+2][j] = v1.z; Bs[kb+3][j] = v1.w;
            Bs[kb+4][j] = v2.x; Bs[kb+5][j] = v2.y; Bs[kb+6][j] = v2.z; Bs[kb+7][j] = v2.w;
        }
        __syncthreads();
        #pragma unroll
        for (int kk = 0; kk < 16; kk++) {
            float4 a1 = *(const float4*)&As[kk][rbase];
            float4 a2 = *(const float4*)&As[kk][rbase + 4];
            float4 b1 = *(const float4*)&Bs[kk][cbase];
            float4 b2 = *(const float4*)&Bs[kk][cbase + 4];
            unsigned long long bp0 = pack2(b1.x, b1.y);
            unsigned long long bp1 = pack2(b1.z, b1.w);
            unsigned long long bp2 = pack2(b2.x, b2.y);
            unsigned long long bp3 = pack2(b2.z, b2.w);
            float ar[8] = {a1.x, a1.y, a1.z, a1.w, a2.x, a2.y, a2.z, a2.w};
            #pragma unroll
            for (int a = 0; a < 8; a++) {
                unsigned long long ap = pack2(ar[a], ar[a]);
                fma2(acc2[a][0], ap, bp0);
                fma2(acc2[a][1], ap, bp1);
                fma2(acc2[a][2], ap, bp2);
                fma2(acc2[a][3], ap, bp3);
            }
        }
        __syncthreads();
    }

    unsigned key = 0u;
    #pragma unroll
    for (int a = 0; a < 8; a++) {
        int row = i0 + rbase + a;
        long off = (long)row * ldc + j0 + cbase;
        float2 p0 = unpack2(acc2[a][0]);
        float2 p1 = unpack2(acc2[a][1]);
        float2 p2 = unpack2(acc2[a][2]);
        float2 p3 = unpack2(acc2[a][3]);
        float4 r1 = make_float4(p0.x, p0.y, p1.x, p1.y);
        float4 r2 = make_float4(p2.x, p2.y, p3.x, p3.y);
        if (EPI == 2) {
            float4 c1 = *(const float4*)(C0 + off);
            float4 c2 = *(const float4*)(C0 + off + 4);
            r1.x = fmaxf(c1.x + r1.x, 0.f); r1.y = fmaxf(c1.y + r1.y, 0.f);
            r1.z = fmaxf(c1.z + r1.z, 0.f); r1.w = fmaxf(c1.w + r1.w, 0.f);
            r2.x = fmaxf(c2.x + r2.x, 0.f); r2.y = fmaxf(c2.y + r2.y, 0.f);
            r2.z = fmaxf(c2.z + r2.z, 0.f); r2.w = fmaxf(c2.w + r2.w, 0.f);
        }
        *(float4*)(C + off)     = r1;
        *(float4*)(C + off + 4) = r2;
        if (EPI == 3) {
            int h = row;
            float vals[8] = {r1.x, r1.y, r1.z, r1.w, r2.x, r2.y, r2.z, r2.w};
            #pragma unroll
            for (int q = 0; q < 8; q++) {
                int m = j0 + cbase + q;
                if (h <= len && m >= 1 && m <= len && h != m) {
                    unsigned k2 = enc_f(vals[q]);
                    if (k2 > key) key = k2;
                }
            }
        }
    }
    if (EPI == 3) {
        #pragma unroll
        for (int o = 16; o; o >>= 1) {
            unsigned ok = __shfl_down_sync(0xffffffffu, key, o);
            if (ok > key) key = ok;
        }
        if ((tid & 31) == 0 && key) atomicMax(&g_cbits[bz], key);
    }
}

// ---------------- build padded Lhat; also cache A into g_A; stash At row0 in g_S ----------------
__global__ void lhat_k(const int* __restrict__ lengths, const float* __restrict__ scores) {
    int i = blockIdx.x, b = blockIdx.y, j = threadIdx.x, len = lengths[b];
    float c = dec_f(g_cbits[b]);
    const float* sc = scores + (size_t)b * NM;
    float* Ab = g_A + (size_t)b * NM;
    float v;
    if (i == NSEQ - 1)      v = (j == NSEQ - 1) ? 1.f : 0.f;
    else if (j == NSEQ - 1) v = 0.f;
    else if (i == 0) {
        int m = j + 1;
        v = (m <= len) ? __expf(sc[m] - c) : 0.f;   // r[j] = A[0][m]
        Ab[m] = v;
        float r1 = (m <= len && m != 1) ? __expf(sc[NSEQ + m] - c) : 0.f;  // A[1][m]
        g_S[b * NSEQ + j] = r1;
        Ab[NSEQ + m] = r1;
    }
    else if (j == i) {
        int m = i + 1;
        float r = (m <= len) ? __expf(sc[m] - c) : 0.f;
        v = r + ((m <= len) ? 0.f : 1.f);           // S added later by diagfix_k
    } else {
        int h = i + 1, m = j + 1;
        float e = (h <= len && m <= len) ? __expf(sc[h * NSEQ + m] - c) : 0.f;
        v = -e;
        Ab[(size_t)h * NSEQ + m] = e;
    }
    g_W[(size_t)b * NM + (size_t)i * NSEQ + j] = v;
}

// ---------------- diag += S, with S_j = row1[j] - sum_{h in [1,510], h!=j} W[h][j] ----------------
__global__ void __launch_bounds__(1024) diagfix_k() {
    int b = blockIdx.y;
    int x = threadIdx.x, y = threadIdx.y;   // (32,32)
    int j = blockIdx.x * 32 + x;
    float* W = g_W + (size_t)b * NM;
    float part = 0.f;
    for (int h = 1 + y; h < NSEQ - 1; h += 32)
        if (h != j) part += W[(size_t)h * NSEQ + j];
    __shared__ float red[32][33];
    red[y][x] = part;
    __syncthreads();
    if (y == 0 && j >= 1 && j <= NSEQ - 2) {
        float s = 0.f;
        #pragma unroll
        for (int k = 0; k < 32; k++) s += red[k][x];
        float S = g_S[b * NSEQ + j] - s;
        W[(size_t)j * NSEQ + j] += S;
    }
}

// ---------------- panel factor: 2 barriers/step, parallel logdet, double-buffered ----------------
__global__ void __launch_bounds__(512) panel_k(int k0) {
    int b = blockIdx.x, tid = threadIdx.x;
    float* W = g_W + (size_t)b * NM;
    float a[NB];
    {
        const float4* src = (const float4*)(W + (size_t)tid * NSEQ + k0);
        #pragma unroll
        for (int q = 0; q < NB/4; q++) {
            float4 v = src[q];
            a[4*q] = v.x; a[4*q+1] = v.y; a[4*q+2] = v.z; a[4*q+3] = v.w;
        }
    }
    __shared__ float s_tmpK[2][NB], s_tmpP[2][NB];
    __shared__ float red_v[2][16]; __shared__ int red_i[2][16];
    __shared__ int s_pivloc[NB];
    __shared__ float s_pv[NB];
    __shared__ int s_src[NSEQ];
    __shared__ int s_aff[64];
    __shared__ int s_cnt;
    if (tid == 0) s_cnt = 0;
    s_src[tid] = tid;

    #pragma unroll
    for (int j = 0; j < NB; j++) {
        int k = k0 + j;
        int db = j & 1;
        // warp-level argmax of |a[j]| over rows >= k
        float best = (tid >= k) ? fabsf(a[j]) : -1.f;
        int bi = tid;
        #pragma unroll
        for (int o = 16; o; o >>= 1) {
            float ov = __shfl_down_sync(0xffffffffu, best, o);
            int   oi = __shfl_down_sync(0xffffffffu, bi, o);
            if (ov > best) { best = ov; bi = oi; }
        }
        if ((tid & 31) == 0) { red_v[db][tid >> 5] = best; red_i[db][tid >> 5] = bi; }
        __syncthreads();                                   // BAR 1
        // every thread redundantly resolves the argmax (all agree: deterministic)
        best = red_v[db][0];
        int p = red_i[db][0];
        #pragma unroll
        for (int w = 1; w < 16; w++) {
            float ov = red_v[db][w];
            if (ov > best) { best = ov; p = red_i[db][w]; }
        }
        // publish rows k and p
        if (tid == k) {
            #pragma unroll
            for (int jj = 0; jj < NB; jj++) s_tmpK[db][jj] = a[jj];
        }
        if (tid == p && p != k) {
            #pragma unroll
            for (int jj = 0; jj < NB; jj++) s_tmpP[db][jj] = a[jj];
        }
        if (tid == 0) s_pivloc[j] = p;
        __syncthreads();                                   // BAR 2
        const float* prow = (p != k) ? s_tmpP[db] : s_tmpK[db];
        float piv = prow[j];
        if (tid == 0) s_pv[j] = piv;
        float pivinv = 1.f / piv;
        if (p != k) {
            if (tid == k) {
                #pragma unroll
                for (int jj = 0; jj < NB; jj++) a[jj] = s_tmpP[db][jj];
            }
            if (tid == p) {
                #pragma unroll
                for (int jj = 0; jj < NB; jj++) a[jj] = s_tmpK[db][jj];
            }
        }
        if (tid == k) {
            #pragma unroll
            for (int jj = 0; jj < NB; jj++) a[jj] = (jj == j) ? pivinv : prow[jj] * pivinv;
        } else {
            float cm = a[j];
            #pragma unroll
            for (int jj = 0; jj < NB; jj++)
                if (jj != j) a[jj] = fmaf(-cm, prow[jj] * pivinv, a[jj]);
            a[j] = -cm * pivinv;
        }
    }
    __syncthreads();   // s_pv / s_pivloc complete

    // parallel logdet: 32 logs + warp-reduce (deterministic tree)
    if (tid < 32) {
        double ld = (tid < NB) ? log(fabs((double)s_pv[tid])) : 0.0;
        #pragma unroll
        for (int o = 16; o; o >>= 1) ld += __shfl_down_sync(0xffffffffu, ld, o);
        if (tid == 0) g_logdet[b] = ((k0 == 0) ? 0.0 : g_logdet[b]) + ld;
    }

    // write F (coalesced per-thread-contiguous)
    {
        float4* fd = (float4*)(g_F + ((size_t)b * NSEQ + tid) * NB);
        #pragma unroll
        for (int q = 0; q < NB/4; q++)
            fd[q] = make_float4(a[4*q], a[4*q+1], a[4*q+2], a[4*q+3]);
    }

    // batched pivot swaps: simulate permutation, gather affected rows
    if (tid == 0) {
        for (int j = 0; j < NB; j++) {
            int k = k0 + j, p = s_pivloc[j];
            if (p != k) { int t = s_src[k]; s_src[k] = s_src[p]; s_src[p] = t; }
        }
    }
    __syncthreads();
    if (s_src[tid] != tid) { int idx = atomicAdd(&s_cnt, 1); s_aff[idx] = tid; }
    __syncthreads();
    int cnt = s_cnt;
    {
        float buf[64];
        #pragma unroll
        for (int aa = 0; aa < 64; aa++)
            if (aa < cnt) buf[aa] = W[(size_t)s_src[s_aff[aa]] * NSEQ + tid];
        #pragma unroll
        for (int aa = 0; aa < 64; aa++)
            if (aa < cnt) W[(size_t)s_aff[aa] * NSEQ + tid] = buf[aa];
    }
    __syncthreads();

    // copy swapped panel rows to g_Wp (coalesced)
    for (int t = tid; t < NB * NSEQ; t += 512) {
        int r = t >> 9, c4 = t & 511;
        g_Wp[(size_t)b * NB * NSEQ + t] = W[(size_t)(k0 + r) * NSEQ + c4];
    }
    // write F into panel columns of W
    {
        float4* wd = (float4*)(W + (size_t)tid * NSEQ + k0);
        #pragma unroll
        for (int q = 0; q < NB/4; q++)
            wd[q] = make_float4(a[4*q], a[4*q+1], a[4*q+2], a[4*q+3]);
    }
    if (tid < NB) g_piv[b * NSEQ + k0 + tid] = s_pivloc[tid];
}

// ---------------- rank-NB trailing update: W = base + F*Wp, full chip, f32x2 ----------------
__global__ void __launch_bounds__(256) upd_k(int k0) {
    int b = blockIdx.z;
    float* W = g_W + (size_t)b * NM;
    const float* F  = g_F  + (size_t)b * NSEQ * NB;
    const float* Wp = g_Wp + (size_t)b * NB * NSEQ;
    __shared__ float Fs[NB][64];
    __shared__ float Bs[NB][64];
    int tid = threadIdx.x;
    int i0 = blockIdx.y * 64, j0 = blockIdx.x * 64;
    {
        int i = tid >> 2, kk = (tid & 3) << 3;
        float4 v1 = *(const float4*)(F + (size_t)(i0 + i) * NB + kk);
        float4 v2 = *(const float4*)(F + (size_t)(i0 + i) * NB + kk + 4);
        Fs[kk+0][i] = v1.x; Fs[kk+1][i] = v1.y; Fs[kk+2][i] = v1.z; Fs[kk+3][i] = v1.w;
        Fs[kk+4][i] = v2.x; Fs[kk+5][i] = v2.y; Fs[kk+6][i] = v2.z; Fs[kk+7][i] = v2.w;
    }
    {
        int kk = tid >> 3, j8 = (tid & 7) << 3;
        *(float4*)&Bs[kk][j8]     = *(const float4*)(Wp + (size_t)kk * NSEQ + j0 + j8);
        *(float4*)&Bs[kk][j8 + 4] = *(const float4*)(Wp + (size_t)kk * NSEQ + j0 + j8 + 4);
    }
    __syncthreads();
    int tx = tid & 15, ty = tid >> 4;
    unsigned long long acc2[4][2] = {};
    #pragma unroll
    for (int kk = 0; kk < NB; kk++) {
        float4 av = *(const float4*)&Fs[kk][ty << 2];
        float4 bv = *(const float4*)&Bs[kk][tx << 2];
        unsigned long long bp0 = pack2(bv.x, bv.y);
        unsigned long long bp1 = pack2(bv.z, bv.w);
        float ar[4] = {av.x, av.y, av.z, av.w};
        #pragma unroll
        for (int a = 0; a < 4; a++) {
            unsigned long long ap = pack2(ar[a], ar[a]);
            fma2(acc2[a][0], ap, bp0);
            fma2(acc2[a][1], ap, bp1);
        }
    }
    int col = j0 + (tx << 2);
    bool pcol = (col >= k0 && col < k0 + NB);
    if (pcol) return;
    #pragma unroll
    for (int a = 0; a < 4; a++) {
        int row = i0 + (ty << 2) + a;
        bool prow = (row >= k0 && row < k0 + NB);
        float4* wp4 = (float4*)(W + (size_t)row * NSEQ + col);
        float2 p0 = unpack2(acc2[a][0]);
        float2 p1 = unpack2(acc2[a][1]);
        float4 r = make_float4(p0.x, p0.y, p1.x, p1.y);
        if (!prow) {
            float4 base = *wp4;
            r.x += base.x; r.y += base.y; r.z += base.z; r.w += base.w;
        }
        *wp4 = r;
    }
}

// ---------------- resolve labels: g_perm = Linv (Linv[L[j]] = j) ----------------
__global__ void __launch_bounds__(512) labels_k() {
    int b = blockIdx.x, tid = threadIdx.x;
    __shared__ int s_L[NSEQ];
    if (tid == 0) {
        for (int j = 0; j < NSEQ; j++) s_L[j] = j;
        for (int k = NSEQ - 1; k >= 0; k--) {
            int p = g_piv[b * NSEQ + k];
            if (p != k) { int t = s_L[k]; s_L[k] = s_L[p]; s_L[p] = t; }
        }
    }
    __syncthreads();
    g_perm[b * NSEQ + s_L[tid]] = tid;
}

// ---------------- coalesced permuted transpose + diag: BT[Linv[j]][i] = C[i][j] ----------------
__global__ void permT_k() {
    int b = blockIdx.z;
    const float* C = g_W + (size_t)b * NM;
    float* BT = g_BT + (size_t)b * NM;
    const int* Linv = g_perm + b * NSEQ;
    __shared__ float sm[32][33];
    int i0 = blockIdx.y * 32, j0 = blockIdx.x * 32;
    int tx = threadIdx.x, ty = threadIdx.y;
    #pragma unroll
    for (int k = 0; k < 4; k++)
        sm[ty + 8*k][tx] = C[(size_t)(i0 + ty + 8*k) * NSEQ + j0 + tx];
    __syncthreads();
    #pragma unroll
    for (int k = 0; k < 4; k++) {
        int j = j0 + ty + 8*k;
        int lj = Linv[j];
        float v = sm[tx][ty + 8*k];
        BT[(size_t)lj * NSEQ + i0 + tx] = v;
        if (lj == i0 + tx) g_diagB[b * NSEQ + lj] = v;
    }
}

// ---------------- marginals Y (straight into out, A from cache) + fp64 dot ----------------
__global__ void __launch_bounds__(512) y_k(const int* __restrict__ lengths,
                                           const float* __restrict__ scores,
                                           float* __restrict__ Yout) {
    int h = blockIdx.x, b = blockIdx.y, m = threadIdx.x;
    int len = lengths[b];
    float s = scores[(size_t)b * NM + (size_t)h * NSEQ + m];
    float y = 0.f;
    if (h <= len && m >= 1 && m <= len && h != m) {
        float A = g_A[(size_t)b * NM + (size_t)h * NSEQ + m];
        float diag = (m >= 2) ? g_diagB[b * NSEQ + (m - 1)] : 0.f;
        float G;
        if (h == 0) G = g_BT[(size_t)b * NM + (m - 1)] + diag;
        else        G = diag - ((h >= 2) ? g_BT[(size_t)b * NM + (size_t)(h - 1) * NSEQ + (m - 1)] : 0.f);
        y = A * G;
    }
    Yout[(size_t)b * NM + (size_t)h * NSEQ + m] = y;

    float v = y * s;
    #pragma unroll
    for (int o = 16; o; o >>= 1) v += __shfl_down_sync(0xffffffffu, v, o);
    __shared__ float ws[16];
    if ((m & 31) == 0) ws[m >> 5] = v;
    __syncthreads();
    if (m < 16) {
        v = ws[m];
        #pragma unroll
        for (int o = 8; o; o >>= 1) v += __shfl_down_sync(0xffffu, v, o);
        if (m == 0) atomicAdd(&g_dotp[b], (double)v);
    }
}

__global__ void fin_k(const int* __restrict__ lengths, float* __restrict__ out) {
    int b = threadIdx.x;
    if (b < BB) {
        float logZ = (float)g_logdet[b] + (float)lengths[b] * dec_f(g_cbits[b]);
        out[(size_t)BB * NM + b] = logZ;
        out[(size_t)2 * BB * NM + BB + b] = logZ - (float)g_dotp[b];
    }
}

extern "C" void kernel_launch(void* const* d_in, const int* in_sizes, int n_in,
                              void* d_out, int out_size) {
    const float* Xh = (const float*)d_in[0];
    const float* Xm = (const float*)d_in[1];
    const int*   lengths = (const int*)d_in[2];
    const float* Wh = (const float*)d_in[3];
    const float* bh = (const float*)d_in[4];
    const float* Wm = (const float*)d_in[5];
    const float* bm = (const float*)d_in[6];
    const float* V  = (const float*)d_in[7];
    float* out = (float*)d_out;

    void* p;
    cudaGetSymbolAddress(&p, g_H0);     float* pH0 = (float*)p;
    cudaGetSymbolAddress(&p, g_M0);     float* pM0 = (float*)p;
    cudaGetSymbolAddress(&p, g_Hb);     float* pHb = (float*)p;
    cudaGetSymbolAddress(&p, g_Mb);     float* pMb = (float*)p;
    cudaGetSymbolAddress(&p, g_T);      float* pT  = (float*)p;

    float* pSc = out;                               // scores block of output
    float* pY  = out + (size_t)BB * NM + BB;        // Y block of output (16B-aligned)

    dim3 gProj(DH / 64, (BB * NSEQ) / 64, 1);

    gemm_k<false, true, 1, true><<<gProj, 256>>>(Xh, Wh, bh, pH0, pHb, BB*NSEQ, DH, DIN, DIN, DIN, DH, 0, 0, 0);
    gemm_k<false, true, 1, true><<<gProj, 256>>>(Xm, Wm, bm, pM0, pMb, BB*NSEQ, DH, DIN, DIN, DIN, DH, 0, 0, 0);

    dim3 gBig128(1, (BB * NSEQ) / 128, 1);
    dim3 gScB(NSEQ / 128, NSEQ / 128, BB);
    dim3 gYMB(1, NSEQ / 128, BB);

    for (int it = 0; it < NITER; it++) {
        float* H = pHb + (size_t)(it & 1) * HS;
        float* M = pMb + (size_t)(it & 1) * HS;
        gemmBig<false, false, 0, false, true><<<gBig128, 256>>>(H, V, nullptr, pT, DH, DH, DH, DH, 0, 0, 0, nullptr);
        gemmBig<false, true, 3, false, false><<<gScB, 256>>>(pT, M, nullptr, pSc, DH, DH, DH, NSEQ,
                                                             (long)NSEQ*DH, (long)NSEQ*DH, (long)NM, lengths);
        lhat_k<<<dim3(NSEQ, BB), NSEQ>>>(lengths, pSc);
        diagfix_k<<<dim3(16, BB), dim3(32, 32)>>>();
        for (int k0 = 0; k0 < NSEQ; k0 += NB) {
            panel_k<<<BB, 512>>>(k0);
            upd_k<<<dim3(8, 8, BB), 256>>>(k0);
        }
        labels_k<<<BB, 512>>>();
        permT_k<<<dim3(16, 16, BB), dim3(32, 8)>>>();
        y_k<<<dim3(NSEQ, BB), NSEQ>>>(lengths, pSc, pY);

        if (it < NITER - 1) {
            float* Hn = pHb + (size_t)((it + 1) & 1) * HS;
            float* Mn = pMb + (size_t)((it + 1) & 1) * HS;
            gemmBig<false, false, 0, true, false><<<gYMB, 256>>>(pY, M, nullptr, pT, NSEQ, NSEQ, DH, DH,
                                                                 (long)NM, (long)NSEQ*DH, (long)NSEQ*DH, lengths);
            gemmBig<false, true, 2, false, false><<<gBig128, 256>>>(pT, V, pH0, Hn, DH, DH, DH, DH, 0, 0, 0, nullptr);
            gemmBig<true, false, 0, true, false><<<gYMB, 256>>>(pY, H, nullptr, pT, NSEQ, NSEQ, DH, DH,
                                                                (long)NM, (long)NSEQ*DH, (long)NSEQ*DH, lengths);
            gemmBig<false, false, 2, false, false><<<gBig128, 256>>>(pT, V, pM0, Mn, DH, DH, DH, DH, 0, 0, 0, nullptr);
        }
    }

    fin_k<<<1, BB>>>(lengths, out);
}

// round 17
// speedup vs baseline: 1.2452x; 1.0163x over previous
#include <cuda_runtime.h>
#include <math.h>

#define BB   32
#define NSEQ 512
#define DIN  256
#define DH   128
#define NITER 10
#define NM   (NSEQ*NSEQ)
#define HS   (BB*NSEQ*DH)
#define NB   32

// ---------------- device scratch (no runtime allocation) ----------------
static __device__ float  g_H0[HS];
static __device__ float  g_M0[HS];
static __device__ float  g_Hb[2*HS];
static __device__ float  g_Mb[2*HS];
static __device__ float  g_T[HS];
static __device__ float  g_W[BB*NM];      // Lhat -> in-place GJ result (cols scrambled)
static __device__ float  g_BT[BB*NM];     // BT[j][i] = Binv[i][j]
static __device__ float  g_A[BB*NM];      // A[h][m] = exp(s-c) cache (written by lhat)
static __device__ float  g_F[BB*NSEQ*NB]; // panel transform, row-major [512][NB]
static __device__ float  g_Wp[BB*NB*NSEQ];// swapped panel rows [NB][512]
static __device__ unsigned g_cbits[BB];   // order-encoded max
static __device__ float  g_S[BB*NSEQ];    // At row 0 (h=1) values, stashed by lhat
static __device__ double g_logdet[BB];
static __device__ double g_dotp[BB];
static __device__ float  g_diagB[BB*NSEQ];
static __device__ int    g_piv[BB*NSEQ];
static __device__ int    g_perm[BB*NSEQ]; // Linv labels

__device__ __forceinline__ unsigned enc_f(float v) {
    unsigned u = __float_as_uint(v);
    return (u & 0x80000000u) ? ~u : (u | 0x80000000u);
}
__device__ __forceinline__ float dec_f(unsigned k) {
    return (k & 0x80000000u) ? __uint_as_float(k & 0x7fffffffu) : __uint_as_float(~k);
}

// ---- packed fp32x2 FMA (Blackwell double-pumped fp32; PTX-only) ----
__device__ __forceinline__ unsigned long long pack2(float lo, float hi) {
    unsigned long long r;
    asm("mov.b64 %0, {%1, %2};" : "=l"(r) : "f"(lo), "f"(hi));
    return r;
}
__device__ __forceinline__ void fma2(unsigned long long& acc, unsigned long long a, unsigned long long b) {
    asm("fma.rn.f32x2 %0, %1, %2, %0;" : "+l"(acc) : "l"(a), "l"(b));
}
__device__ __forceinline__ float2 unpack2(unsigned long long p) {
    float lo, hi;
    asm("mov.b64 {%0, %1}, %2;" : "=f"(lo), "=f"(hi) : "l"(p));
    return make_float2(lo, hi);
}

// ---------------- 64x64 GEMM (startup projections; fused relu copy) ----------------
template<bool TA, bool TB, int EPI, bool RELU2>
__global__ void __launch_bounds__(256) gemm_k(
    const float* __restrict__ A, const float* __restrict__ B,
    const float* __restrict__ C0, float* __restrict__ C, float* __restrict__ C2,
    int M, int N, int K, int lda, int ldb, int ldc,
    long sA, long sB, long sC)
{
    int bz = blockIdx.z;
    A += (long)bz * sA;  B += (long)bz * sB;  C += (long)bz * sC;
    __shared__ float As[16][64];
    __shared__ float Bs[16][64];
    int tid = threadIdx.x;
    int i0 = blockIdx.y * 64, j0 = blockIdx.x * 64;
    int tx = tid & 15, ty = tid >> 4;
    float acc[4][4] = {};
    for (int k0 = 0; k0 < K; k0 += 16) {
        if (!TA) {
            int i = tid >> 2, kk = (tid & 3) << 2;
            float4 v = *(const float4*)(A + (long)(i0 + i) * lda + k0 + kk);
            As[kk + 0][i] = v.x; As[kk + 1][i] = v.y; As[kk + 2][i] = v.z; As[kk + 3][i] = v.w;
        } else {
            int kk = tid >> 4, i4 = (tid & 15) << 2;
            float4 v = *(const float4*)(A + (long)(k0 + kk) * lda + i0 + i4);
            *(float4*)&As[kk][i4] = v;
        }
        if (!TB) {
            int kk = tid >> 4, j4 = (tid & 15) << 2;
            float4 v = *(const float4*)(B + (long)(k0 + kk) * ldb + j0 + j4);
            *(float4*)&Bs[kk][j4] = v;
        } else {
            int j = tid >> 2, kk = (tid & 3) << 2;
            float4 v = *(const float4*)(B + (long)(j0 + j) * ldb + k0 + kk);
            Bs[kk + 0][j] = v.x; Bs[kk + 1][j] = v.y; Bs[kk + 2][j] = v.z; Bs[kk + 3][j] = v.w;
        }
        __syncthreads();
        #pragma unroll
        for (int kk = 0; kk < 16; kk++) {
            float4 av = *(const float4*)&As[kk][ty << 2];
            float4 bv = *(const float4*)&Bs[kk][tx << 2];
            float ar[4] = {av.x, av.y, av.z, av.w};
            float br[4] = {bv.x, bv.y, bv.z, bv.w};
            #pragma unroll
            for (int a = 0; a < 4; a++)
                #pragma unroll
                for (int q = 0; q < 4; q++)
                    acc[a][q] = fmaf(ar[a], br[q], acc[a][q]);
        }
        __syncthreads();
    }
    #pragma unroll
    for (int a = 0; a < 4; a++) {
        int row = i0 + (ty << 2) + a;
        long off = (long)row * ldc + j0 + (tx << 2);
        float4 r = make_float4(acc[a][0], acc[a][1], acc[a][2], acc[a][3]);
        if (EPI == 1) {
            float4 bb = *(const float4*)(C0 + j0 + (tx << 2));
            r.x += bb.x; r.y += bb.y; r.z += bb.z; r.w += bb.w;
        }
        *(float4*)(C + off) = r;
        if (RELU2) {
            float4 rr = make_float4(fmaxf(r.x, 0.f), fmaxf(r.y, 0.f), fmaxf(r.z, 0.f), fmaxf(r.w, 0.f));
            *(float4*)(C2 + off) = rr;
        }
    }
}

// ---------------- 128x128 GEMM, split 8x8 micro (conflict-free LDS), f32x2 FMA ----------------
// Thread owns rows {4ty+a, 64+4ty+a}, cols {4tx+q, 64+4tx+q}  ->  LDS at 4-float stride.
template<bool TA, bool TB, int EPI, bool LENA, bool INIT0>
__global__ void __launch_bounds__(256) gemmBig(
    const float* __restrict__ A, const float* __restrict__ B,
    const float* __restrict__ C0, float* __restrict__ C,
    int K, int lda, int ldb, int ldc,
    long sA, long sB, long sC,
    const int* __restrict__ lengths)
{
    int bz = blockIdx.z;
    int tid = threadIdx.x;
    if (INIT0) {
        if (blockIdx.y == 0 && blockIdx.x == 0 && bz == 0 && tid < BB) {
            g_cbits[tid] = 0u; g_dotp[tid] = 0.0;
        }
    }
    A += (long)bz * sA;  B += (long)bz * sB;  C += (long)bz * sC;
    __shared__ float As[16][128];
    __shared__ float Bs[16][128];
    int i0 = blockIdx.y * 128, j0 = blockIdx.x * 128;
    int ty = tid >> 4, tx = tid & 15;
    int r0 = ty << 2, r1 = 64 + (ty << 2);      // row halves
    int c0 = tx << 2, c1 = 64 + (tx << 2);      // col halves

    int Kend = K;
    int len = 0;
    if (LENA || EPI == 3) len = lengths[bz];
    if (LENA) {
        if (i0 > len) {
            #pragma unroll
            for (int a = 0; a < 8; a++) {
                int row = i0 + ((a < 4) ? (r0 + a) : (r1 + a - 4));
                *(float4*)(C + (long)row * ldc + j0 + c0) = make_float4(0.f, 0.f, 0.f, 0.f);
                *(float4*)(C + (long)row * ldc + j0 + c1) = make_float4(0.f, 0.f, 0.f, 0.f);
            }
            return;
        }
        Kend = min(K, (len + 16) & ~15);
    }

    unsigned long long acc2[8][4] = {};   // [row a][col-pair: c0,c0+2,c1,c1+2]
    for (int k0 = 0; k0 < Kend; k0 += 16) {
        if (!TA) {
            int i = tid >> 1, kb = (tid & 1) << 3;
            float4 v1 = *(const float4*)(A + (long)(i0 + i) * lda + k0 + kb);
            float4 v2 = *(const float4*)(A + (long)(i0 + i) * lda + k0 + kb + 4);
            As[kb+0][i] = v1.x; As[kb+1][i] = v1.y; As[kb+2][i] = v1.z; As[kb+3][i] = v1.w;
            As[kb+4][i] = v2.x; As[kb+5][i] = v2.y; As[kb+6][i] = v2.z; As[kb+7][i] = v2.w;
        } else {
            int kk = tid >> 4, i8 = (tid & 15) << 3;
            *(float4*)&As[kk][i8]     = *(const float4*)(A + (long)(k0 + kk) * lda + i0 + i8);
            *(float4*)&As[kk][i8 + 4] = *(const float4*)(A + (long)(k0 + kk) * lda + i0 + i8 + 4);
        }
        if (!TB) {
            int kk = tid >> 4, j8 = (tid & 15) << 3;
            *(float4*)&Bs[kk][j8]     = *(const float4*)(B + (long)(k0 + kk) * ldb + j0 + j8);
            *(float4*)&Bs[kk][j8 + 4] = *(const float4*)(B + (long)(k0 + kk) * ldb + j0 + j8 + 4);
        } else {
            int j = tid >> 1, kb = (tid & 1) << 3;
            float4 v1 = *(const float4*)(B + (long)(j0 + j) * ldb + k0 + kb);
            float4 v2 = *(const float4*)(B + (long)(j0 + j) * ldb + k0 + kb + 4);
            Bs[kb+0][j] = v1.x; Bs[kb+1][j] = v1.y; Bs[kb+2][j] = v1.z; Bs[kb+3][j] = v1.w;
            Bs[kb+4][j] = v2.x; Bs[kb+5][j] = v2.y; Bs[kb+6][j] = v2.z; Bs[kb+7][j] = v2.w;
        }
        __syncthreads();
        #pragma unroll
        for (int kk = 0; kk < 16; kk++) {
            float4 a1 = *(const float4*)&As[kk][r0];
            float4 a2 = *(const float4*)&As[kk][r1];
            float4 b1 = *(const float4*)&Bs[kk][c0];
            float4 b2 = *(const float4*)&Bs[kk][c1];
            unsigned long long bp0 = pack2(b1.x, b1.y);
            unsigned long long bp1 = pack2(b1.z, b1.w);
            unsigned long long bp2 = pack2(b2.x, b2.y);
            unsigned long long bp3 = pack2(b2.z, b2.w);
            float ar[8] = {a1.x, a1.y, a1.z, a1.w, a2.x, a2.y, a2.z, a2.w};
            #pragma unroll
            for (int a = 0; a < 8; a++) {
                unsigned long long ap = pack2(ar[a], ar[a]);
                fma2(acc2[a][0], ap, bp0);
                fma2(acc2[a][1], ap, bp1);
                fma2(acc2[a][2], ap, bp2);
                fma2(acc2[a][3], ap, bp3);
            }
        }
        __syncthreads();
    }

    unsigned key = 0u;
    #pragma unroll
    for (int a = 0; a < 8; a++) {
        int row = i0 + ((a < 4) ? (r0 + a) : (r1 + a - 4));
        long off0 = (long)row * ldc + j0 + c0;
        long off1 = (long)row * ldc + j0 + c1;
        float2 p0 = unpack2(acc2[a][0]);
        float2 p1 = unpack2(acc2[a][1]);
        float2 p2 = unpack2(acc2[a][2]);
        float2 p3 = unpack2(acc2[a][3]);
        float4 rA = make_float4(p0.x, p0.y, p1.x, p1.y);   // cols c0..c0+3
        float4 rB = make_float4(p2.x, p2.y, p3.x, p3.y);   // cols c1..c1+3
        if (EPI == 2) {
            float4 cA = *(const float4*)(C0 + off0);
            float4 cB = *(const float4*)(C0 + off1);
            rA.x = fmaxf(cA.x + rA.x, 0.f); rA.y = fmaxf(cA.y + rA.y, 0.f);
            rA.z = fmaxf(cA.z + rA.z, 0.f); rA.w = fmaxf(cA.w + rA.w, 0.f);
            rB.x = fmaxf(cB.x + rB.x, 0.f); rB.y = fmaxf(cB.y + rB.y, 0.f);
            rB.z = fmaxf(cB.z + rB.z, 0.f); rB.w = fmaxf(cB.w + rB.w, 0.f);
        }
        *(float4*)(C + off0) = rA;
        *(float4*)(C + off1) = rB;
        if (EPI == 3) {
            int h = row;
            float valsA[4] = {rA.x, rA.y, rA.z, rA.w};
            float valsB[4] = {rB.x, rB.y, rB.z, rB.w};
            #pragma unroll
            for (int q = 0; q < 4; q++) {
                int mA = j0 + c0 + q;
                if (h <= len && mA >= 1 && mA <= len && h != mA) {
                    unsigned k2 = enc_f(valsA[q]);
                    if (k2 > key) key = k2;
                }
                int mB = j0 + c1 + q;
                if (h <= len && mB >= 1 && mB <= len && h != mB) {
                    unsigned k2 = enc_f(valsB[q]);
                    if (k2 > key) key = k2;
                }
            }
        }
    }
    if (EPI == 3) {
        #pragma unroll
        for (int o = 16; o; o >>= 1) {
            unsigned ok = __shfl_down_sync(0xffffffffu, key, o);
            if (ok > key) key = ok;
        }
        if ((tid & 31) == 0 && key) atomicMax(&g_cbits[bz], key);
    }
}

// ---------------- build padded Lhat; also cache A into g_A; stash At row0 in g_S ----------------
__global__ void lhat_k(const int* __restrict__ lengths, const float* __restrict__ scores) {
    int i = blockIdx.x, b = blockIdx.y, j = threadIdx.x, len = lengths[b];
    float c = dec_f(g_cbits[b]);
    const float* sc = scores + (size_t)b * NM;
    float* Ab = g_A + (size_t)b * NM;
    float v;
    if (i == NSEQ - 1)      v = (j == NSEQ - 1) ? 1.f : 0.f;
    else if (j == NSEQ - 1) v = 0.f;
    else if (i == 0) {
        int m = j + 1;
        v = (m <= len) ? __expf(sc[m] - c) : 0.f;   // r[j] = A[0][m]
        Ab[m] = v;
        float r1 = (m <= len && m != 1) ? __expf(sc[NSEQ + m] - c) : 0.f;  // A[1][m]
        g_S[b * NSEQ + j] = r1;
        Ab[NSEQ + m] = r1;
    }
    else if (j == i) {
        int m = i + 1;
        float r = (m <= len) ? __expf(sc[m] - c) : 0.f;
        v = r + ((m <= len) ? 0.f : 1.f);           // S added later by diagfix_k
    } else {
        int h = i + 1, m = j + 1;
        float e = (h <= len && m <= len) ? __expf(sc[h * NSEQ + m] - c) : 0.f;
        v = -e;
        Ab[(size_t)h * NSEQ + m] = e;
    }
    g_W[(size_t)b * NM + (size_t)i * NSEQ + j] = v;
}

// ---------------- diag += S, with S_j = row1[j] - sum_{h in [1,510], h!=j} W[h][j] ----------------
__global__ void __launch_bounds__(1024) diagfix_k() {
    int b = blockIdx.y;
    int x = threadIdx.x, y = threadIdx.y;   // (32,32)
    int j = blockIdx.x * 32 + x;
    float* W = g_W + (size_t)b * NM;
    float part = 0.f;
    for (int h = 1 + y; h < NSEQ - 1; h += 32)
        if (h != j) part += W[(size_t)h * NSEQ + j];
    __shared__ float red[32][33];
    red[y][x] = part;
    __syncthreads();
    if (y == 0 && j >= 1 && j <= NSEQ - 2) {
        float s = 0.f;
        #pragma unroll
        for (int k = 0; k < 32; k++) s += red[k][x];
        float S = g_S[b * NSEQ + j] - s;
        W[(size_t)j * NSEQ + j] += S;
    }
}

// ---------------- panel factor: 2 barriers/step, parallel logdet, double-buffered ----------------
__global__ void __launch_bounds__(512) panel_k(int k0) {
    int b = blockIdx.x, tid = threadIdx.x;
    float* W = g_W + (size_t)b * NM;
    float a[NB];
    {
        const float4* src = (const float4*)(W + (size_t)tid * NSEQ + k0);
        #pragma unroll
        for (int q = 0; q < NB/4; q++) {
            float4 v = src[q];
            a[4*q] = v.x; a[4*q+1] = v.y; a[4*q+2] = v.z; a[4*q+3] = v.w;
        }
    }
    __shared__ float s_tmpK[2][NB], s_tmpP[2][NB];
    __shared__ float red_v[2][16]; __shared__ int red_i[2][16];
    __shared__ int s_pivloc[NB];
    __shared__ float s_pv[NB];
    __shared__ int s_src[NSEQ];
    __shared__ int s_aff[64];
    __shared__ int s_cnt;
    if (tid == 0) s_cnt = 0;
    s_src[tid] = tid;

    #pragma unroll
    for (int j = 0; j < NB; j++) {
        int k = k0 + j;
        int db = j & 1;
        float best = (tid >= k) ? fabsf(a[j]) : -1.f;
        int bi = tid;
        #pragma unroll
        for (int o = 16; o; o >>= 1) {
            float ov = __shfl_down_sync(0xffffffffu, best, o);
            int   oi = __shfl_down_sync(0xffffffffu, bi, o);
            if (ov > best) { best = ov; bi = oi; }
        }
        if ((tid & 31) == 0) { red_v[db][tid >> 5] = best; red_i[db][tid >> 5] = bi; }
        __syncthreads();                                   // BAR 1
        best = red_v[db][0];
        int p = red_i[db][0];
        #pragma unroll
        for (int w = 1; w < 16; w++) {
            float ov = red_v[db][w];
            if (ov > best) { best = ov; p = red_i[db][w]; }
        }
        if (tid == k) {
            #pragma unroll
            for (int jj = 0; jj < NB; jj++) s_tmpK[db][jj] = a[jj];
        }
        if (tid == p && p != k) {
            #pragma unroll
            for (int jj = 0; jj < NB; jj++) s_tmpP[db][jj] = a[jj];
        }
        if (tid == 0) s_pivloc[j] = p;
        __syncthreads();                                   // BAR 2
        const float* prow = (p != k) ? s_tmpP[db] : s_tmpK[db];
        float piv = prow[j];
        if (tid == 0) s_pv[j] = piv;
        float pivinv = 1.f / piv;
        if (p != k) {
            if (tid == k) {
                #pragma unroll
                for (int jj = 0; jj < NB; jj++) a[jj] = s_tmpP[db][jj];
            }
            if (tid == p) {
                #pragma unroll
                for (int jj = 0; jj < NB; jj++) a[jj] = s_tmpK[db][jj];
            }
        }
        if (tid == k) {
            #pragma unroll
            for (int jj = 0; jj < NB; jj++) a[jj] = (jj == j) ? pivinv : prow[jj] * pivinv;
        } else {
            float cm = a[j];
            #pragma unroll
            for (int jj = 0; jj < NB; jj++)
                if (jj != j) a[jj] = fmaf(-cm, prow[jj] * pivinv, a[jj]);
            a[j] = -cm * pivinv;
        }
    }
    __syncthreads();

    if (tid < 32) {
        double ld = (tid < NB) ? log(fabs((double)s_pv[tid])) : 0.0;
        #pragma unroll
        for (int o = 16; o; o >>= 1) ld += __shfl_down_sync(0xffffffffu, ld, o);
        if (tid == 0) g_logdet[b] = ((k0 == 0) ? 0.0 : g_logdet[b]) + ld;
    }

    {
        float4* fd = (float4*)(g_F + ((size_t)b * NSEQ + tid) * NB);
        #pragma unroll
        for (int q = 0; q < NB/4; q++)
            fd[q] = make_float4(a[4*q], a[4*q+1], a[4*q+2], a[4*q+3]);
    }

    if (tid == 0) {
        for (int j = 0; j < NB; j++) {
            int k = k0 + j, p = s_pivloc[j];
            if (p != k) { int t = s_src[k]; s_src[k] = s_src[p]; s_src[p] = t; }
        }
    }
    __syncthreads();
    if (s_src[tid] != tid) { int idx = atomicAdd(&s_cnt, 1); s_aff[idx] = tid; }
    __syncthreads();
    int cnt = s_cnt;
    {
        float buf[64];
        #pragma unroll
        for (int aa = 0; aa < 64; aa++)
            if (aa < cnt) buf[aa] = W[(size_t)s_src[s_aff[aa]] * NSEQ + tid];
        #pragma unroll
        for (int aa = 0; aa < 64; aa++)
            if (aa < cnt) W[(size_t)s_aff[aa] * NSEQ + tid] = buf[aa];
    }
    __syncthreads();

    for (int t = tid; t < NB * NSEQ; t += 512) {
        int r = t >> 9, c4 = t & 511;
        g_Wp[(size_t)b * NB * NSEQ + t] = W[(size_t)(k0 + r) * NSEQ + c4];
    }
    {
        float4* wd = (float4*)(W + (size_t)tid * NSEQ + k0);
        #pragma unroll
        for (int q = 0; q < NB/4; q++)
            wd[q] = make_float4(a[4*q], a[4*q+1], a[4*q+2], a[4*q+3]);
    }
    if (tid < NB) g_piv[b * NSEQ + k0 + tid] = s_pivloc[tid];
}

// ---------------- rank-NB trailing update: W = base + F*Wp, full chip, f32x2 ----------------
__global__ void __launch_bounds__(256) upd_k(int k0) {
    int b = blockIdx.z;
    float* W = g_W + (size_t)b * NM;
    const float* F  = g_F  + (size_t)b * NSEQ * NB;
    const float* Wp = g_Wp + (size_t)b * NB * NSEQ;
    __shared__ float Fs[NB][64];
    __shared__ float Bs[NB][64];
    int tid = threadIdx.x;
    int i0 = blockIdx.y * 64, j0 = blockIdx.x * 64;
    {
        int i = tid >> 2, kk = (tid & 3) << 3;
        float4 v1 = *(const float4*)(F + (size_t)(i0 + i) * NB + kk);
        float4 v2 = *(const float4*)(F + (size_t)(i0 + i) * NB + kk + 4);
        Fs[kk+0][i] = v1.x; Fs[kk+1][i] = v1.y; Fs[kk+2][i] = v1.z; Fs[kk+3][i] = v1.w;
        Fs[kk+4][i] = v2.x; Fs[kk+5][i] = v2.y; Fs[kk+6][i] = v2.z; Fs[kk+7][i] = v2.w;
    }
    {
        int kk = tid >> 3, j8 = (tid & 7) << 3;
        *(float4*)&Bs[kk][j8]     = *(const float4*)(Wp + (size_t)kk * NSEQ + j0 + j8);
        *(float4*)&Bs[kk][j8 + 4] = *(const float4*)(Wp + (size_t)kk * NSEQ + j0 + j8 + 4);
    }
    __syncthreads();
    int tx = tid & 15, ty = tid >> 4;
    unsigned long long acc2[4][2] = {};
    #pragma unroll
    for (int kk = 0; kk < NB; kk++) {
        float4 av = *(const float4*)&Fs[kk][ty << 2];
        float4 bv = *(const float4*)&Bs[kk][tx << 2];
        unsigned long long bp0 = pack2(bv.x, bv.y);
        unsigned long long bp1 = pack2(bv.z, bv.w);
        float ar[4] = {av.x, av.y, av.z, av.w};
        #pragma unroll
        for (int a = 0; a < 4; a++) {
            unsigned long long ap = pack2(ar[a], ar[a]);
            fma2(acc2[a][0], ap, bp0);
            fma2(acc2[a][1], ap, bp1);
        }
    }
    int col = j0 + (tx << 2);
    bool pcol = (col >= k0 && col < k0 + NB);
    if (pcol) return;
    #pragma unroll
    for (int a = 0; a < 4; a++) {
        int row = i0 + (ty << 2) + a;
        bool prow = (row >= k0 && row < k0 + NB);
        float4* wp4 = (float4*)(W + (size_t)row * NSEQ + col);
        float2 p0 = unpack2(acc2[a][0]);
        float2 p1 = unpack2(acc2[a][1]);
        float4 r = make_float4(p0.x, p0.y, p1.x, p1.y);
        if (!prow) {
            float4 base = *wp4;
            r.x += base.x; r.y += base.y; r.z += base.z; r.w += base.w;
        }
        *wp4 = r;
    }
}

// ---------------- resolve labels: g_perm = Linv (Linv[L[j]] = j) ----------------
__global__ void __launch_bounds__(512) labels_k() {
    int b = blockIdx.x, tid = threadIdx.x;
    __shared__ int s_L[NSEQ];
    if (tid == 0) {
        for (int j = 0; j < NSEQ; j++) s_L[j] = j;
        for (int k = NSEQ - 1; k >= 0; k--) {
            int p = g_piv[b * NSEQ + k];
            if (p != k) { int t = s_L[k]; s_L[k] = s_L[p]; s_L[p] = t; }
        }
    }
    __syncthreads();
    g_perm[b * NSEQ + s_L[tid]] = tid;
}

// ---------------- coalesced permuted transpose + diag: BT[Linv[j]][i] = C[i][j] ----------------
__global__ void permT_k() {
    int b = blockIdx.z;
    const float* C = g_W + (size_t)b * NM;
    float* BT = g_BT + (size_t)b * NM;
    const int* Linv = g_perm + b * NSEQ;
    __shared__ float sm[32][33];
    int i0 = blockIdx.y * 32, j0 = blockIdx.x * 32;
    int tx = threadIdx.x, ty = threadIdx.y;
    #pragma unroll
    for (int k = 0; k < 4; k++)
        sm[ty + 8*k][tx] = C[(size_t)(i0 + ty + 8*k) * NSEQ + j0 + tx];
    __syncthreads();
    #pragma unroll
    for (int k = 0; k < 4; k++) {
        int j = j0 + ty + 8*k;
        int lj = Linv[j];
        float v = sm[tx][ty + 8*k];
        BT[(size_t)lj * NSEQ + i0 + tx] = v;
        if (lj == i0 + tx) g_diagB[b * NSEQ + lj] = v;
    }
}

// ---------------- marginals Y (straight into out, A from cache) + fp64 dot ----------------
__global__ void __launch_bounds__(512) y_k(const int* __restrict__ lengths,
                                           const float* __restrict__ scores,
                                           float* __restrict__ Yout) {
    int h = blockIdx.x, b = blockIdx.y, m = threadIdx.x;
    int len = lengths[b];
    float s = scores[(size_t)b * NM + (size_t)h * NSEQ + m];
    float y = 0.f;
    if (h <= len && m >= 1 && m <= len && h != m) {
        float A = g_A[(size_t)b * NM + (size_t)h * NSEQ + m];
        float diag = (m >= 2) ? g_diagB[b * NSEQ + (m - 1)] : 0.f;
        float G;
        if (h == 0) G = g_BT[(size_t)b * NM + (m - 1)] + diag;
        else        G = diag - ((h >= 2) ? g_BT[(size_t)b * NM + (size_t)(h - 1) * NSEQ + (m - 1)] : 0.f);
        y = A * G;
    }
    Yout[(size_t)b * NM + (size_t)h * NSEQ + m] = y;

    float v = y * s;
    #pragma unroll
    for (int o = 16; o; o >>= 1) v += __shfl_down_sync(0xffffffffu, v, o);
    __shared__ float ws[16];
    if ((m & 31) == 0) ws[m >> 5] = v;
    __syncthreads();
    if (m < 16) {
        v = ws[m];
        #pragma unroll
        for (int o = 8; o; o >>= 1) v += __shfl_down_sync(0xffffu, v, o);
        if (m == 0) atomicAdd(&g_dotp[b], (double)v);
    }
}

__global__ void fin_k(const int* __restrict__ lengths, float* __restrict__ out) {
    int b = threadIdx.x;
    if (b < BB) {
        float logZ = (float)g_logdet[b] + (float)lengths[b] * dec_f(g_cbits[b]);
        out[(size_t)BB * NM + b] = logZ;
        out[(size_t)2 * BB * NM + BB + b] = logZ - (float)g_dotp[b];
    }
}

extern "C" void kernel_launch(void* const* d_in, const int* in_sizes, int n_in,
                              void* d_out, int out_size) {
    const float* Xh = (const float*)d_in[0];
    const float* Xm = (const float*)d_in[1];
    const int*   lengths = (const int*)d_in[2];
    const float* Wh = (const float*)d_in[3];
    const float* bh = (const float*)d_in[4];
    const float* Wm = (const float*)d_in[5];
    const float* bm = (const float*)d_in[6];
    const float* V  = (const float*)d_in[7];
    float* out = (float*)d_out;

    void* p;
    cudaGetSymbolAddress(&p, g_H0);     float* pH0 = (float*)p;
    cudaGetSymbolAddress(&p, g_M0);     float* pM0 = (float*)p;
    cudaGetSymbolAddress(&p, g_Hb);     float* pHb = (float*)p;
    cudaGetSymbolAddress(&p, g_Mb);     float* pMb = (float*)p;
    cudaGetSymbolAddress(&p, g_T);      float* pT  = (float*)p;

    float* pSc = out;                               // scores block of output
    float* pY  = out + (size_t)BB * NM + BB;        // Y block of output (16B-aligned)

    dim3 gProj(DH / 64, (BB * NSEQ) / 64, 1);

    gemm_k<false, true, 1, true><<<gProj, 256>>>(Xh, Wh, bh, pH0, pHb, BB*NSEQ, DH, DIN, DIN, DIN, DH, 0, 0, 0);
    gemm_k<false, true, 1, true><<<gProj, 256>>>(Xm, Wm, bm, pM0, pMb, BB*NSEQ, DH, DIN, DIN, DIN, DH, 0, 0, 0);

    dim3 gBig128(1, (BB * NSEQ) / 128, 1);
    dim3 gScB(NSEQ / 128, NSEQ / 128, BB);
    dim3 gYMB(1, NSEQ / 128, BB);

    for (int it = 0; it < NITER; it++) {
        float* H = pHb + (size_t)(it & 1) * HS;
        float* M = pMb + (size_t)(it & 1) * HS;
        gemmBig<false, false, 0, false, true><<<gBig128, 256>>>(H, V, nullptr, pT, DH, DH, DH, DH, 0, 0, 0, nullptr);
        gemmBig<false, true, 3, false, false><<<gScB, 256>>>(pT, M, nullptr, pSc, DH, DH, DH, NSEQ,
                                                             (long)NSEQ*DH, (long)NSEQ*DH, (long)NM, lengths);
        lhat_k<<<dim3(NSEQ, BB), NSEQ>>>(lengths, pSc);
        diagfix_k<<<dim3(16, BB), dim3(32, 32)>>>();
        for (int k0 = 0; k0 < NSEQ; k0 += NB) {
            panel_k<<<BB, 512>>>(k0);
            upd_k<<<dim3(8, 8, BB), 256>>>(k0);
        }
        labels_k<<<BB, 512>>>();
        permT_k<<<dim3(16, 16, BB), dim3(32, 8)>>>();
        y_k<<<dim3(NSEQ, BB), NSEQ>>>(lengths, pSc, pY);

        if (it < NITER - 1) {
            float* Hn = pHb + (size_t)((it + 1) & 1) * HS;
            float* Mn = pMb + (size_t)((it + 1) & 1) * HS;
            gemmBig<false, false, 0, true, false><<<gYMB, 256>>>(pY, M, nullptr, pT, NSEQ, NSEQ, DH, DH,
                                                                 (long)NM, (long)NSEQ*DH, (long)NSEQ*DH, lengths);
            gemmBig<false, true, 2, false, false><<<gBig128, 256>>>(pT, V, pH0, Hn, DH, DH, DH, DH, 0, 0, 0, nullptr);
            gemmBig<true, false, 0, true, false><<<gYMB, 256>>>(pY, H, nullptr, pT, NSEQ, NSEQ, DH, DH,
                                                                (long)NM, (long)NSEQ*DH, (long)NSEQ*DH, lengths);
            gemmBig<false, false, 2, false, false><<<gBig128, 256>>>(pT, V, pM0, Mn, DH, DH, DH, DH, 0, 0, 0, nullptr);
        }
    }

    fin_k<<<1, BB>>>(lengths, out);
}